// round 6
// baseline (speedup 1.0000x reference)
#include <cuda_runtime.h>
#include <math.h>

// Problem constants
#define NN_ 50000
#define EE_ 600000
#define HH_ 128
#define FF_ 256
#define QQ_ 64
#define NH_ (NN_ * HH_)

// ---------------- scratch (device globals; no dynamic allocation) ----------
__device__ float g_h0 [4 * NH_];
__device__ float g_h1 [4 * NH_];
__device__ float g_hA [4 * NH_];
__device__ float g_agg[8 * NH_];     // (c,r) pairs; reused for phase A and B

__device__ int   g_cnt_in [8 * NN_];
__device__ int   g_cnt_out[8 * NN_];
__device__ int   g_cursor [8 * NN_];
__device__ int   g_off    [8 * (NN_ + 1)];
__device__ int   g_csr    [8 * EE_];
__device__ float g_din    [8 * NN_];
__device__ float g_dout   [8 * NN_];

// ---------------- helpers ---------------------------------------------------
__device__ __forceinline__ const int* edge_ptr_dev(const int* e_attr, const int* e_stru,
                                                   int p, int which) {
    int c = p >> 1, r = p & 1;
    int sign = c >> 1;
    const int* E = (c & 1) ? e_stru : e_attr;
    return E + ((size_t)((sign * 2 + r) * 2 + which)) * EE_;
}

// ---------------- CSR-build kernels (batched over 8 pairs) ------------------
__global__ void zero_int_kernel(int* p, int n) {
    for (int i = blockIdx.x * blockDim.x + threadIdx.x; i < n; i += gridDim.x * blockDim.x)
        p[i] = 0;
}

__global__ void hist_all_kernel(const int* __restrict__ e_attr, const int* __restrict__ e_stru,
                                int* __restrict__ cnt_out, int* __restrict__ cnt_in) {
    int p = blockIdx.y;
    const int* src = edge_ptr_dev(e_attr, e_stru, p, 0);
    const int* dst = edge_ptr_dev(e_attr, e_stru, p, 1);
    int* co = cnt_out + p * NN_;
    int* ci = cnt_in  + p * NN_;
    for (int i = blockIdx.x * blockDim.x + threadIdx.x; i < EE_; i += gridDim.x * blockDim.x) {
        atomicAdd(&co[src[i]], 1);
        atomicAdd(&ci[dst[i]], 1);
    }
}

__global__ void deg_all_kernel(const int* __restrict__ cin, const int* __restrict__ cout,
                               float* __restrict__ din, float* __restrict__ dout) {
    for (int i = blockIdx.x * blockDim.x + threadIdx.x; i < 8 * NN_; i += gridDim.x * blockDim.x) {
        int a = cin[i];  if (a < 1) a = 1;
        int b = cout[i]; if (b < 1) b = 1;
        din [i] = rsqrtf((float)a);
        dout[i] = rsqrtf((float)b);
    }
}

__global__ void scan_all_kernel(const int* __restrict__ cnt_all, int* __restrict__ off_all,
                                int* __restrict__ cur_all) {
    __shared__ int sh[1024];
    const int p = blockIdx.x;
    const int* cnt = cnt_all + p * NN_;
    int* off = off_all + p * (NN_ + 1);
    int* cur = cur_all + p * NN_;
    const int t  = threadIdx.x;
    const int CH = (NN_ + 1023) / 1024;
    const int base = t * CH;
    int s = 0;
    for (int i = 0; i < CH; i++) { int idx = base + i; if (idx < NN_) s += cnt[idx]; }
    sh[t] = s;
    __syncthreads();
    for (int d = 1; d < 1024; d <<= 1) {
        int v = (t >= d) ? sh[t - d] : 0;
        __syncthreads();
        sh[t] += v;
        __syncthreads();
    }
    int run = (t == 0) ? 0 : sh[t - 1];
    for (int i = 0; i < CH; i++) {
        int idx = base + i;
        if (idx < NN_) { off[idx] = run; cur[idx] = run; run += cnt[idx]; }
    }
    if (t == 0) off[NN_] = sh[1023];
}

__global__ void scatter_all_kernel(const int* __restrict__ e_attr, const int* __restrict__ e_stru,
                                   int* __restrict__ cursor, int* __restrict__ csr) {
    int p = blockIdx.y;
    const int* src = edge_ptr_dev(e_attr, e_stru, p, 0);
    const int* dst = edge_ptr_dev(e_attr, e_stru, p, 1);
    int* cu = cursor + p * NN_;
    int* cs = csr + (size_t)p * EE_;
    for (int i = blockIdx.x * blockDim.x + threadIdx.x; i < EE_; i += gridDim.x * blockDim.x) {
        int pos = atomicAdd(&cu[dst[i]], 1);
        cs[pos] = src[i];
    }
}

// ---------------- batched CSR gather (warp per node, float4) ----------------
__global__ void gather_all_kernel(const float* __restrict__ hin_base,
                                  const int* __restrict__ off_all,
                                  const int* __restrict__ csr_all,
                                  const float* __restrict__ dout_all,
                                  float* __restrict__ agg) {
    int p = blockIdx.y;
    int c = p >> 1;
    const float* h = hin_base + (size_t)c * NH_;
    const int* off = off_all + p * (NN_ + 1);
    const int* csr = csr_all + (size_t)p * EE_;
    const float* dout = dout_all + p * NN_;
    float* out = agg + (size_t)p * NH_;

    int warp = (blockIdx.x * blockDim.x + threadIdx.x) >> 5;
    int lane = threadIdx.x & 31;
    if (warp >= NN_) return;
    int b = off[warp], e = off[warp + 1];
    const float4* h4 = (const float4*)h;
    float ax = 0.f, ay = 0.f, az = 0.f, aw = 0.f;
    int i = b;
    for (; i + 1 < e; i += 2) {
        int s0 = csr[i], s1 = csr[i + 1];
        float w0 = dout[s0], w1 = dout[s1];
        float4 v0 = h4[(size_t)s0 * 32 + lane];
        float4 v1 = h4[(size_t)s1 * 32 + lane];
        ax += w0 * v0.x + w1 * v1.x;
        ay += w0 * v0.y + w1 * v1.y;
        az += w0 * v0.z + w1 * v1.z;
        aw += w0 * v0.w + w1 * v1.w;
    }
    if (i < e) {
        int s0 = csr[i];
        float w0 = dout[s0];
        float4 v0 = h4[(size_t)s0 * 32 + lane];
        ax += w0 * v0.x; ay += w0 * v0.y; az += w0 * v0.z; aw += w0 * v0.w;
    }
    float4 r; r.x = ax; r.y = ay; r.z = az; r.w = aw;
    ((float4*)out)[(size_t)warp * 32 + lane] = r;
}

// ---------------- tf32 helpers ----------------------------------------------
__device__ __forceinline__ unsigned f2tf(float f) {
    unsigned u;
    asm("cvt.rna.tf32.f32 %0, %1;" : "=r"(u) : "f"(f));
    return u;
}

__device__ __forceinline__ void mma8(float* c, const unsigned* a, unsigned b0, unsigned b1) {
    asm volatile(
        "mma.sync.aligned.m16n8k8.row.col.f32.tf32.tf32.f32 "
        "{%0,%1,%2,%3},{%4,%5,%6,%7},{%8,%9},{%0,%1,%2,%3};"
        : "+f"(c[0]), "+f"(c[1]), "+f"(c[2]), "+f"(c[3])
        : "r"(a[0]), "r"(a[1]), "r"(a[2]), "r"(a[3]), "r"(b0), "r"(b1));
}

#define LDSP 136    // pad 8: bank = 8*tig + grp -> conflict-free fragment reads

// ---------------- h0 GEMM: h0 = tanh(x @ Wf[s]^T), batched over 4 runs ------
__global__ __launch_bounds__(256)
void h0_gemm_kernel(const float* __restrict__ x_attr, const float* __restrict__ x_stru,
                    const float* __restrict__ Wf, float* __restrict__ h0b) {
    constexpr int BK = 32;
    __shared__ unsigned As[BK][LDSP];
    __shared__ unsigned Bs[BK][LDSP];

    const int c = blockIdx.y;
    const int s = c >> 1;
    const float* A = (c & 1) ? x_stru : x_attr;
    const float* B = Wf + (size_t)s * HH_ * FF_;
    float* C = h0b + (size_t)c * NH_;

    const int tid  = threadIdx.x;
    const int lane = tid & 31;
    const int warp = tid >> 5;
    const int grp  = lane >> 2;
    const int tig  = lane & 3;
    const int wm   = warp >> 1;
    const int wn   = warp & 1;
    const int mbase = wm * 32;
    const int nbase = wn * 64;
    const int block_m = blockIdx.x * 128;

    float acc[2][8][4];
#pragma unroll
    for (int mf = 0; mf < 2; mf++)
#pragma unroll
        for (int nf = 0; nf < 8; nf++)
#pragma unroll
            for (int q = 0; q < 4; q++) acc[mf][nf][q] = 0.f;

    for (int k0 = 0; k0 < FF_; k0 += BK) {
        {
            int row = tid & 127;
            int f4b = tid >> 7;
            int gm = block_m + row;
            bool ok = (gm < NN_);
            const float* ap = A + (size_t)gm * FF_ + k0;
#pragma unroll
            for (int ii = 0; ii < 4; ii++) {
                int f4 = f4b + ii * 2;
                float4 v;
                if (ok) v = *(const float4*)(ap + f4 * 4);
                else { v.x = v.y = v.z = v.w = 0.f; }
                int kc = f4 * 4;
                As[kc + 0][row] = f2tf(v.x);
                As[kc + 1][row] = f2tf(v.y);
                As[kc + 2][row] = f2tf(v.z);
                As[kc + 3][row] = f2tf(v.w);
            }
        }
        {
            int n = tid & 127;
            int f4b = tid >> 7;
            const float* bp = B + (size_t)n * FF_ + k0;
#pragma unroll
            for (int ii = 0; ii < 4; ii++) {
                int f4 = f4b + ii * 2;
                float4 v = *(const float4*)(bp + f4 * 4);
                int kc = f4 * 4;
                Bs[kc + 0][n] = f2tf(v.x);
                Bs[kc + 1][n] = f2tf(v.y);
                Bs[kc + 2][n] = f2tf(v.z);
                Bs[kc + 3][n] = f2tf(v.w);
            }
        }
        __syncthreads();
#pragma unroll
        for (int k8 = 0; k8 < BK; k8 += 8) {
            unsigned a[2][4];
#pragma unroll
            for (int mf = 0; mf < 2; mf++) {
                int r0 = mbase + mf * 16 + grp;
                a[mf][0] = As[k8 + tig][r0];
                a[mf][1] = As[k8 + tig][r0 + 8];
                a[mf][2] = As[k8 + tig + 4][r0];
                a[mf][3] = As[k8 + tig + 4][r0 + 8];
            }
#pragma unroll
            for (int nf = 0; nf < 8; nf++) {
                int n = nbase + nf * 8 + grp;
                unsigned b0 = Bs[k8 + tig][n];
                unsigned b1 = Bs[k8 + tig + 4][n];
                mma8(acc[0][nf], a[0], b0, b1);
                mma8(acc[1][nf], a[1], b0, b1);
            }
        }
        __syncthreads();
    }
#pragma unroll
    for (int mf = 0; mf < 2; mf++) {
        int r0 = block_m + mbase + mf * 16 + grp;
#pragma unroll
        for (int nf = 0; nf < 8; nf++) {
            int col = nbase + nf * 8 + tig * 2;
#pragma unroll
            for (int half = 0; half < 2; half++) {
                int r = r0 + half * 8;
                if (r >= NN_) continue;
                float2 st;
                st.x = tanhf(acc[mf][nf][half * 2 + 0]);
                st.y = tanhf(acc[mf][nf][half * 2 + 1]);
                *(float2*)(C + (size_t)r * HH_ + col) = st;
            }
        }
    }
}

// ---------------- fused het-layer: conv(r=0,1) + attn scores + softmax + combine
// PHASE 0: blockIdx.y = q in 0..7: c=q>>1, li=q&1 (li=0 -> l=1 -> h1; li=1 -> l=0 -> hA)
// PHASE 1: blockIdx.y = c in 0..3, l=1; result kept in smem, then fused final
//          GEMM y = [h0|h1|h2] @ Wc^T written straight to yout.
template <int PHASE>
__global__ __launch_bounds__(256)
void het_pair_kernel(const float* __restrict__ agg,
                     const float* __restrict__ convW, const float* __restrict__ convB,
                     const float* __restrict__ attnW1, const float* __restrict__ attnB1,
                     const float* __restrict__ attnW2,
                     const float* __restrict__ din_all,
                     const float* __restrict__ h0b, const float* __restrict__ h1b,
                     const float* __restrict__ Wc,
                     float* __restrict__ h1out, float* __restrict__ hAout,
                     float* __restrict__ yout) {
    constexpr int BK = 32;
    extern __shared__ char smraw[];
    unsigned (*As)[LDSP]  = (unsigned(*)[LDSP])(smraw);
    unsigned (*Bs)[LDSP]  = (unsigned(*)[LDSP])(smraw + 32 * LDSP * 4);
    unsigned (*HSs)[LDSP] = (unsigned(*)[LDSP])(smraw + 64 * LDSP * 4);
    float* s_sm = (float*)(smraw + (64 + 128) * LDSP * 4);   // [2][128]

    const int q = blockIdx.y;
    int c, l;
    float* hout = nullptr;
    if (PHASE == 0) {
        c = q >> 1;
        int li = q & 1;
        l = li ? 0 : 1;
        hout = (li == 0 ? h1out : hAout) + (size_t)c * NH_;
    } else {
        c = q;
        l = 1;
    }
    const int s = c >> 1;

    const int tid  = threadIdx.x;
    const int lane = tid & 31;
    const int warp = tid >> 5;
    const int grp  = lane >> 2;
    const int tig  = lane & 3;
    const int wm   = warp >> 1;
    const int wn   = warp & 1;
    const int mbase = wm * 32;
    const int block_m = blockIdx.x * 128;

    s_sm[tid] = 0.f;   // 256 floats = both relations' score rows

    float accA[2][8][4], accB[2][8][4];

    for (int r = 0; r < 2; r++) {
        float (*acc)[8][4] = (r == 0) ? accA : accB;
        const int p = c * 2 + r;
        const float* A    = agg + (size_t)p * NH_;
        const float* W    = convW + (size_t)((s * 2 + l) * 2 + r) * HH_ * HH_;
        const float* bias = convB + (size_t)((s * 2 + l) * 2 + r) * HH_;
        const float* W1   = attnW1 + (size_t)(s * 2 + l) * HH_ * QQ_;
        const float* b1   = attnB1 + (size_t)(s * 2 + l) * QQ_;
        const float* w2   = attnW2 + (size_t)(s * 2 + l) * QQ_;
        const float* din  = din_all + p * NN_;

#pragma unroll
        for (int mf = 0; mf < 2; mf++)
#pragma unroll
            for (int nf = 0; nf < 8; nf++)
#pragma unroll
                for (int qq = 0; qq < 4; qq++) acc[mf][nf][qq] = 0.f;

        // ---- stage 1: conv GEMM (K=128, N=128)
        for (int k0 = 0; k0 < HH_; k0 += BK) {
            {
                int row = tid & 127;
                int f4b = tid >> 7;
                int gm = block_m + row;
                bool ok = (gm < NN_);
                const float* ap = A + (size_t)gm * HH_ + k0;
#pragma unroll
                for (int ii = 0; ii < 4; ii++) {
                    int f4 = f4b + ii * 2;
                    float4 v;
                    if (ok) v = *(const float4*)(ap + f4 * 4);
                    else { v.x = v.y = v.z = v.w = 0.f; }
                    int kc = f4 * 4;
                    As[kc + 0][row] = f2tf(v.x);
                    As[kc + 1][row] = f2tf(v.y);
                    As[kc + 2][row] = f2tf(v.z);
                    As[kc + 3][row] = f2tf(v.w);
                }
            }
            {
                int f4 = tid & 31;
                int kb = tid >> 5;
#pragma unroll
                for (int ii = 0; ii < 4; ii++) {
                    int k = kb + ii * 8;
                    float4 v = *(const float4*)(W + (size_t)(k0 + k) * HH_ + f4 * 4);
                    uint4 w;
                    w.x = f2tf(v.x); w.y = f2tf(v.y); w.z = f2tf(v.z); w.w = f2tf(v.w);
                    *(uint4*)&Bs[k][f4 * 4] = w;
                }
            }
            __syncthreads();
#pragma unroll
            for (int k8 = 0; k8 < BK; k8 += 8) {
                unsigned a[2][4];
#pragma unroll
                for (int mf = 0; mf < 2; mf++) {
                    int r0 = mbase + mf * 16 + grp;
                    a[mf][0] = As[k8 + tig][r0];
                    a[mf][1] = As[k8 + tig][r0 + 8];
                    a[mf][2] = As[k8 + tig + 4][r0];
                    a[mf][3] = As[k8 + tig + 4][r0 + 8];
                }
#pragma unroll
                for (int nf = 0; nf < 8; nf++) {
                    int n = wn * 64 + nf * 8 + grp;
                    unsigned b0 = Bs[k8 + tig][n];
                    unsigned b1 = Bs[k8 + tig + 4][n];
                    mma8(acc[0][nf], a[0], b0, b1);
                    mma8(acc[1][nf], a[1], b0, b1);
                }
            }
            __syncthreads();
        }

        // ---- stage-1 epilogue: acc = acc*din + bias (in regs); tf32 copy to HSs
#pragma unroll
        for (int mf = 0; mf < 2; mf++) {
            int rl0 = mbase + mf * 16 + grp;
#pragma unroll
            for (int nf = 0; nf < 8; nf++) {
                int col = wn * 64 + nf * 8 + tig * 2;
                float bc0 = bias[col], bc1 = bias[col + 1];
#pragma unroll
                for (int half = 0; half < 2; half++) {
                    int rl = rl0 + half * 8;
                    int rg = block_m + rl;
                    float rs = (rg < NN_) ? din[rg] : 0.f;
                    float v0 = acc[mf][nf][half * 2 + 0] * rs + bc0;
                    float v1 = acc[mf][nf][half * 2 + 1] * rs + bc1;
                    acc[mf][nf][half * 2 + 0] = v0;
                    acc[mf][nf][half * 2 + 1] = v1;
                    HSs[col][rl]     = f2tf(v0);
                    HSs[col + 1][rl] = f2tf(v1);
                }
            }
        }
        __syncthreads();

        // ---- stage 2: t = tanh(hs@W1 + b1); score = t . w2
        float acc2[2][4][4];
#pragma unroll
        for (int mf = 0; mf < 2; mf++)
#pragma unroll
            for (int nf = 0; nf < 4; nf++)
#pragma unroll
                for (int qq = 0; qq < 4; qq++) acc2[mf][nf][qq] = 0.f;

        for (int k0 = 0; k0 < HH_; k0 += BK) {
            {
                int f4 = tid & 15;
                int kb = tid >> 4;
#pragma unroll
                for (int ii = 0; ii < 2; ii++) {
                    int k = kb + ii * 16;
                    float4 v = *(const float4*)(W1 + (size_t)(k0 + k) * QQ_ + f4 * 4);
                    uint4 w;
                    w.x = f2tf(v.x); w.y = f2tf(v.y); w.z = f2tf(v.z); w.w = f2tf(v.w);
                    *(uint4*)&Bs[k][f4 * 4] = w;
                }
            }
            __syncthreads();
#pragma unroll
            for (int k8 = 0; k8 < BK; k8 += 8) {
                unsigned a[2][4];
#pragma unroll
                for (int mf = 0; mf < 2; mf++) {
                    int r0 = mbase + mf * 16 + grp;
                    a[mf][0] = HSs[k0 + k8 + tig][r0];
                    a[mf][1] = HSs[k0 + k8 + tig][r0 + 8];
                    a[mf][2] = HSs[k0 + k8 + tig + 4][r0];
                    a[mf][3] = HSs[k0 + k8 + tig + 4][r0 + 8];
                }
#pragma unroll
                for (int nf = 0; nf < 4; nf++) {
                    int n = wn * 32 + nf * 8 + grp;
                    unsigned b0 = Bs[k8 + tig][n];
                    unsigned b1 = Bs[k8 + tig + 4][n];
                    mma8(acc2[0][nf], a[0], b0, b1);
                    mma8(acc2[1][nf], a[1], b0, b1);
                }
            }
            __syncthreads();
        }

        float part[2][2] = {{0.f, 0.f}, {0.f, 0.f}};
#pragma unroll
        for (int mf = 0; mf < 2; mf++)
#pragma unroll
            for (int nf = 0; nf < 4; nf++) {
                int col = wn * 32 + nf * 8 + tig * 2;
                float bc0 = b1[col], bc1 = b1[col + 1];
                float w20 = w2[col], w21 = w2[col + 1];
#pragma unroll
                for (int half = 0; half < 2; half++) {
                    float v0 = tanhf(acc2[mf][nf][half * 2 + 0] + bc0);
                    float v1 = tanhf(acc2[mf][nf][half * 2 + 1] + bc1);
                    part[mf][half] += v0 * w20 + v1 * w21;
                }
            }
#pragma unroll
        for (int o = 1; o <= 2; o <<= 1) {
#pragma unroll
            for (int mf = 0; mf < 2; mf++)
#pragma unroll
                for (int half = 0; half < 2; half++)
                    part[mf][half] += __shfl_xor_sync(0xffffffffu, part[mf][half], o);
        }
        if (tig == 0) {
#pragma unroll
            for (int mf = 0; mf < 2; mf++)
#pragma unroll
                for (int half = 0; half < 2; half++)
                    atomicAdd(&s_sm[r * 128 + mbase + mf * 16 + grp + half * 8],
                              part[mf][half]);
        }
        __syncthreads();   // scores for this r complete; safe to reuse As/Bs/HSs next r
    }

    // ---- softmax over relations + combine (in registers) ----
#pragma unroll
    for (int mf = 0; mf < 2; mf++) {
        int rl0 = mbase + mf * 16 + grp;
#pragma unroll
        for (int half = 0; half < 2; half++) {
            int rl = rl0 + half * 8;
            float sv0 = s_sm[rl], sv1 = s_sm[128 + rl];
            float m = fmaxf(sv0, sv1);
            float e0 = expf(sv0 - m), e1 = expf(sv1 - m);
            float a0 = e0 / (e0 + e1), a1 = 1.f - a0;
            int rg = block_m + rl;
#pragma unroll
            for (int nf = 0; nf < 8; nf++) {
                int col = wn * 64 + nf * 8 + tig * 2;
                float v0 = a0 * accA[mf][nf][half * 2 + 0] + a1 * accB[mf][nf][half * 2 + 0];
                float v1 = a0 * accA[mf][nf][half * 2 + 1] + a1 * accB[mf][nf][half * 2 + 1];
                if (PHASE == 0) {
                    if (rg < NN_) {
                        float2 st; st.x = v0; st.y = v1;
                        *(float2*)(hout + (size_t)rg * HH_ + col) = st;
                    }
                } else {
                    HSs[col][rl]     = f2tf(v0);   // h2 tile, transposed tf32
                    HSs[col + 1][rl] = f2tf(v1);
                }
            }
        }
    }

    if (PHASE == 1) {
        // ---- stage 3: y = [h0|h1|h2] @ Wc[s]^T (h2 from smem) ----
        __syncthreads();
        const float* B = Wc + (size_t)s * HH_ * (3 * HH_);
        float acc3[2][8][4];
#pragma unroll
        for (int mf = 0; mf < 2; mf++)
#pragma unroll
            for (int nf = 0; nf < 8; nf++)
#pragma unroll
                for (int qq = 0; qq < 4; qq++) acc3[mf][nf][qq] = 0.f;

        for (int k0 = 0; k0 < 3 * HH_; k0 += BK) {
            int seg = k0 >> 7;
            int kseg = k0 & 127;
            if (seg < 2) {
                const float* A = ((seg == 0) ? h0b : h1b) + (size_t)c * NH_;
                int row = tid & 127;
                int f4b = tid >> 7;
                int gm = block_m + row;
                bool ok = (gm < NN_);
                const float* ap = A + (size_t)gm * HH_ + kseg;
#pragma unroll
                for (int ii = 0; ii < 4; ii++) {
                    int f4 = f4b + ii * 2;
                    float4 v;
                    if (ok) v = *(const float4*)(ap + f4 * 4);
                    else { v.x = v.y = v.z = v.w = 0.f; }
                    int kc = f4 * 4;
                    As[kc + 0][row] = f2tf(v.x);
                    As[kc + 1][row] = f2tf(v.y);
                    As[kc + 2][row] = f2tf(v.z);
                    As[kc + 3][row] = f2tf(v.w);
                }
            }
            {
                int n = tid & 127;
                int f4b = tid >> 7;
                const float* bp = B + (size_t)n * (3 * HH_) + k0;
#pragma unroll
                for (int ii = 0; ii < 4; ii++) {
                    int f4 = f4b + ii * 2;
                    float4 v = *(const float4*)(bp + f4 * 4);
                    int kc = f4 * 4;
                    Bs[kc + 0][n] = f2tf(v.x);
                    Bs[kc + 1][n] = f2tf(v.y);
                    Bs[kc + 2][n] = f2tf(v.z);
                    Bs[kc + 3][n] = f2tf(v.w);
                }
            }
            __syncthreads();
#pragma unroll
            for (int k8 = 0; k8 < BK; k8 += 8) {
                unsigned a[2][4];
#pragma unroll
                for (int mf = 0; mf < 2; mf++) {
                    int r0 = mbase + mf * 16 + grp;
                    if (seg < 2) {
                        a[mf][0] = As[k8 + tig][r0];
                        a[mf][1] = As[k8 + tig][r0 + 8];
                        a[mf][2] = As[k8 + tig + 4][r0];
                        a[mf][3] = As[k8 + tig + 4][r0 + 8];
                    } else {
                        a[mf][0] = HSs[kseg + k8 + tig][r0];
                        a[mf][1] = HSs[kseg + k8 + tig][r0 + 8];
                        a[mf][2] = HSs[kseg + k8 + tig + 4][r0];
                        a[mf][3] = HSs[kseg + k8 + tig + 4][r0 + 8];
                    }
                }
#pragma unroll
                for (int nf = 0; nf < 8; nf++) {
                    int n = wn * 64 + nf * 8 + grp;
                    unsigned b0 = Bs[k8 + tig][n];
                    unsigned b1 = Bs[k8 + tig + 4][n];
                    mma8(acc3[0][nf], a[0], b0, b1);
                    mma8(acc3[1][nf], a[1], b0, b1);
                }
            }
            __syncthreads();
        }
        float* C = yout + (size_t)c * NH_;
#pragma unroll
        for (int mf = 0; mf < 2; mf++) {
            int r0 = block_m + mbase + mf * 16 + grp;
#pragma unroll
            for (int nf = 0; nf < 8; nf++) {
                int col = wn * 64 + nf * 8 + tig * 2;
#pragma unroll
                for (int half = 0; half < 2; half++) {
                    int rr = r0 + half * 8;
                    if (rr >= NN_) continue;
                    float2 st;
                    st.x = acc3[mf][nf][half * 2 + 0];
                    st.y = acc3[mf][nf][half * 2 + 1];
                    *(float2*)(C + (size_t)rr * HH_ + col) = st;
                }
            }
        }
    }
}

// ---------------- host orchestration ----------------------------------------
extern "C" void kernel_launch(void* const* d_in, const int* in_sizes, int n_in,
                              void* d_out, int out_size) {
    const float* x_attr  = (const float*)d_in[0];
    const float* x_stru  = (const float*)d_in[1];
    const int*   e_attr  = (const int*)  d_in[2];
    const int*   e_stru  = (const int*)  d_in[3];
    const float* Wf      = (const float*)d_in[4];   // (2,H,F)
    const float* convW   = (const float*)d_in[5];   // (2,2,2,H,H)
    const float* convB   = (const float*)d_in[6];   // (2,2,2,H)
    const float* attnW1  = (const float*)d_in[7];   // (2,2,H,Q)
    const float* attnB1  = (const float*)d_in[8];   // (2,2,Q)
    const float* attnW2  = (const float*)d_in[9];   // (2,2,Q)
    const float* Wc      = (const float*)d_in[10];  // (2,H,3H)
    float* out = (float*)d_out;

    float *h0, *h1, *hA, *agg, *din, *dout;
    int *cnt_in, *cnt_out, *cursor, *off, *csr;
    cudaGetSymbolAddress((void**)&h0,  g_h0);
    cudaGetSymbolAddress((void**)&h1,  g_h1);
    cudaGetSymbolAddress((void**)&hA,  g_hA);
    cudaGetSymbolAddress((void**)&agg, g_agg);
    cudaGetSymbolAddress((void**)&din,  g_din);
    cudaGetSymbolAddress((void**)&dout, g_dout);
    cudaGetSymbolAddress((void**)&cnt_in,  g_cnt_in);
    cudaGetSymbolAddress((void**)&cnt_out, g_cnt_out);
    cudaGetSymbolAddress((void**)&cursor,  g_cursor);
    cudaGetSymbolAddress((void**)&off, g_off);
    cudaGetSymbolAddress((void**)&csr, g_csr);

    const int TB = 256;
    const int gridM = (NN_ + 127) / 128;
    const int gridWarp = (NN_ + 7) / 8;
    const int HET_SMEM = (64 + 128) * LDSP * 4 + 2 * 128 * 4;   // ~105.5 KB
    cudaFuncSetAttribute(het_pair_kernel<0>, cudaFuncAttributeMaxDynamicSharedMemorySize, HET_SMEM);
    cudaFuncSetAttribute(het_pair_kernel<1>, cudaFuncAttributeMaxDynamicSharedMemorySize, HET_SMEM);

    // 1) zero histogram counters
    zero_int_kernel<<<512, TB>>>(cnt_in, 8 * NN_);
    zero_int_kernel<<<512, TB>>>(cnt_out, 8 * NN_);

    // 2) h0 for all 4 runs
    h0_gemm_kernel<<<dim3(gridM, 4), TB>>>(x_attr, x_stru, Wf, h0);

    // 3) CSR build, all 8 pairs batched
    hist_all_kernel<<<dim3(256, 8), TB>>>(e_attr, e_stru, cnt_out, cnt_in);
    deg_all_kernel<<<(8 * NN_ + 255) / 256, TB>>>(cnt_in, cnt_out, din, dout);
    scan_all_kernel<<<8, 1024>>>(cnt_in, off, cursor);
    scatter_all_kernel<<<dim3(256, 8), TB>>>(e_attr, e_stru, cursor, csr);

    // 4) phase A: gather over h0, fused het (8 combos) -> h1, hA
    gather_all_kernel<<<dim3(gridWarp, 8), TB>>>(h0, off, csr, dout, agg);
    het_pair_kernel<0><<<dim3(gridM, 8), TB, HET_SMEM>>>(
        agg, convW, convB, attnW1, attnB1, attnW2, din, h0, h1, Wc, h1, hA, out);

    // 5) phase B: gather over hA, fused het (4) + final concat GEMM -> out
    gather_all_kernel<<<dim3(gridWarp, 8), TB>>>(hA, off, csr, dout, agg);
    het_pair_kernel<1><<<dim3(gridM, 4), TB, HET_SMEM>>>(
        agg, convW, convB, attnW1, attnB1, attnW2, din, h0, h1, Wc, h1, hA, out);
}

// round 7
// speedup vs baseline: 1.1061x; 1.1061x over previous
#include <cuda_runtime.h>
#include <math.h>

// Problem constants
#define NN_ 50000
#define EE_ 600000
#define HH_ 128
#define FF_ 256
#define QQ_ 64
#define NH_ (NN_ * HH_)

// ---------------- scratch (device globals; no dynamic allocation) ----------
__device__ float g_h0 [4 * NH_];
__device__ float g_h1 [4 * NH_];
__device__ float g_hA [4 * NH_];
__device__ float g_agg[8 * NH_];     // (c,r) pairs; reused for phase A and B

__device__ int   g_cnt_in [8 * NN_];
__device__ int   g_cnt_out[8 * NN_];
__device__ int   g_cursor [8 * NN_];
__device__ int   g_off    [8 * (NN_ + 1)];
__device__ int   g_csr    [8 * EE_];
__device__ float g_din    [8 * NN_];
__device__ float g_dout   [8 * NN_];

// ---------------- helpers ---------------------------------------------------
__device__ __forceinline__ const int* edge_ptr_dev(const int* e_attr, const int* e_stru,
                                                   int p, int which) {
    int c = p >> 1, r = p & 1;
    int sign = c >> 1;
    const int* E = (c & 1) ? e_stru : e_attr;
    return E + ((size_t)((sign * 2 + r) * 2 + which)) * EE_;
}

// ---------------- CSR-build kernels (batched over 8 pairs) ------------------
__global__ void zero_int_kernel(int* p, int n) {
    for (int i = blockIdx.x * blockDim.x + threadIdx.x; i < n; i += gridDim.x * blockDim.x)
        p[i] = 0;
}

__global__ void hist_all_kernel(const int* __restrict__ e_attr, const int* __restrict__ e_stru,
                                int* __restrict__ cnt_out, int* __restrict__ cnt_in) {
    int p = blockIdx.y;
    const int* src = edge_ptr_dev(e_attr, e_stru, p, 0);
    const int* dst = edge_ptr_dev(e_attr, e_stru, p, 1);
    int* co = cnt_out + p * NN_;
    int* ci = cnt_in  + p * NN_;
    for (int i = blockIdx.x * blockDim.x + threadIdx.x; i < EE_; i += gridDim.x * blockDim.x) {
        atomicAdd(&co[src[i]], 1);
        atomicAdd(&ci[dst[i]], 1);
    }
}

__global__ void deg_all_kernel(const int* __restrict__ cin, const int* __restrict__ cout,
                               float* __restrict__ din, float* __restrict__ dout) {
    for (int i = blockIdx.x * blockDim.x + threadIdx.x; i < 8 * NN_; i += gridDim.x * blockDim.x) {
        int a = cin[i];  if (a < 1) a = 1;
        int b = cout[i]; if (b < 1) b = 1;
        din [i] = rsqrtf((float)a);
        dout[i] = rsqrtf((float)b);
    }
}

__global__ void scan_all_kernel(const int* __restrict__ cnt_all, int* __restrict__ off_all,
                                int* __restrict__ cur_all) {
    __shared__ int sh[1024];
    const int p = blockIdx.x;
    const int* cnt = cnt_all + p * NN_;
    int* off = off_all + p * (NN_ + 1);
    int* cur = cur_all + p * NN_;
    const int t  = threadIdx.x;
    const int CH = (NN_ + 1023) / 1024;
    const int base = t * CH;
    int s = 0;
    for (int i = 0; i < CH; i++) { int idx = base + i; if (idx < NN_) s += cnt[idx]; }
    sh[t] = s;
    __syncthreads();
    for (int d = 1; d < 1024; d <<= 1) {
        int v = (t >= d) ? sh[t - d] : 0;
        __syncthreads();
        sh[t] += v;
        __syncthreads();
    }
    int run = (t == 0) ? 0 : sh[t - 1];
    for (int i = 0; i < CH; i++) {
        int idx = base + i;
        if (idx < NN_) { off[idx] = run; cur[idx] = run; run += cnt[idx]; }
    }
    if (t == 0) off[NN_] = sh[1023];
}

__global__ void scatter_all_kernel(const int* __restrict__ e_attr, const int* __restrict__ e_stru,
                                   int* __restrict__ cursor, int* __restrict__ csr) {
    int p = blockIdx.y;
    const int* src = edge_ptr_dev(e_attr, e_stru, p, 0);
    const int* dst = edge_ptr_dev(e_attr, e_stru, p, 1);
    int* cu = cursor + p * NN_;
    int* cs = csr + (size_t)p * EE_;
    for (int i = blockIdx.x * blockDim.x + threadIdx.x; i < EE_; i += gridDim.x * blockDim.x) {
        int pos = atomicAdd(&cu[dst[i]], 1);
        cs[pos] = src[i];
    }
}

// ---------------- batched CSR gather (warp per node, float4) ----------------
__global__ void gather_all_kernel(const float* __restrict__ hin_base,
                                  const int* __restrict__ off_all,
                                  const int* __restrict__ csr_all,
                                  const float* __restrict__ dout_all,
                                  float* __restrict__ agg) {
    int p = blockIdx.y;
    int c = p >> 1;
    const float* h = hin_base + (size_t)c * NH_;
    const int* off = off_all + p * (NN_ + 1);
    const int* csr = csr_all + (size_t)p * EE_;
    const float* dout = dout_all + p * NN_;
    float* out = agg + (size_t)p * NH_;

    int warp = (blockIdx.x * blockDim.x + threadIdx.x) >> 5;
    int lane = threadIdx.x & 31;
    if (warp >= NN_) return;
    int b = off[warp], e = off[warp + 1];
    const float4* h4 = (const float4*)h;
    float ax = 0.f, ay = 0.f, az = 0.f, aw = 0.f;
    int i = b;
    for (; i + 1 < e; i += 2) {
        int s0 = csr[i], s1 = csr[i + 1];
        float w0 = dout[s0], w1 = dout[s1];
        float4 v0 = h4[(size_t)s0 * 32 + lane];
        float4 v1 = h4[(size_t)s1 * 32 + lane];
        ax += w0 * v0.x + w1 * v1.x;
        ay += w0 * v0.y + w1 * v1.y;
        az += w0 * v0.z + w1 * v1.z;
        aw += w0 * v0.w + w1 * v1.w;
    }
    if (i < e) {
        int s0 = csr[i];
        float w0 = dout[s0];
        float4 v0 = h4[(size_t)s0 * 32 + lane];
        ax += w0 * v0.x; ay += w0 * v0.y; az += w0 * v0.z; aw += w0 * v0.w;
    }
    float4 r; r.x = ax; r.y = ay; r.z = az; r.w = aw;
    ((float4*)out)[(size_t)warp * 32 + lane] = r;
}

// ---------------- tf32 helpers ----------------------------------------------
__device__ __forceinline__ unsigned f2tf(float f) {
    unsigned u;
    asm("cvt.rna.tf32.f32 %0, %1;" : "=r"(u) : "f"(f));
    return u;
}

__device__ __forceinline__ void mma8(float* c, const unsigned* a, unsigned b0, unsigned b1) {
    asm volatile(
        "mma.sync.aligned.m16n8k8.row.col.f32.tf32.tf32.f32 "
        "{%0,%1,%2,%3},{%4,%5,%6,%7},{%8,%9},{%0,%1,%2,%3};"
        : "+f"(c[0]), "+f"(c[1]), "+f"(c[2]), "+f"(c[3])
        : "r"(a[0]), "r"(a[1]), "r"(a[2]), "r"(a[3]), "r"(b0), "r"(b1));
}

#define LDSP 136    // pad 8: bank = 8*tig + grp -> conflict-free fragment reads

// ---------------- h0 GEMM: h0 = tanh(x @ Wf[s]^T), batched over 4 runs ------
__global__ __launch_bounds__(256)
void h0_gemm_kernel(const float* __restrict__ x_attr, const float* __restrict__ x_stru,
                    const float* __restrict__ Wf, float* __restrict__ h0b) {
    constexpr int BK = 32;
    __shared__ unsigned As[BK][LDSP];
    __shared__ unsigned Bs[BK][LDSP];

    const int c = blockIdx.y;
    const int s = c >> 1;
    const float* A = (c & 1) ? x_stru : x_attr;
    const float* B = Wf + (size_t)s * HH_ * FF_;
    float* C = h0b + (size_t)c * NH_;

    const int tid  = threadIdx.x;
    const int lane = tid & 31;
    const int warp = tid >> 5;
    const int grp  = lane >> 2;
    const int tig  = lane & 3;
    const int wm   = warp >> 1;
    const int wn   = warp & 1;
    const int mbase = wm * 32;
    const int nbase = wn * 64;
    const int block_m = blockIdx.x * 128;

    float acc[2][8][4];
#pragma unroll
    for (int mf = 0; mf < 2; mf++)
#pragma unroll
        for (int nf = 0; nf < 8; nf++)
#pragma unroll
            for (int q = 0; q < 4; q++) acc[mf][nf][q] = 0.f;

    for (int k0 = 0; k0 < FF_; k0 += BK) {
        {
            int row = tid & 127;
            int f4b = tid >> 7;
            int gm = block_m + row;
            bool ok = (gm < NN_);
            const float* ap = A + (size_t)gm * FF_ + k0;
#pragma unroll
            for (int ii = 0; ii < 4; ii++) {
                int f4 = f4b + ii * 2;
                float4 v;
                if (ok) v = *(const float4*)(ap + f4 * 4);
                else { v.x = v.y = v.z = v.w = 0.f; }
                int kc = f4 * 4;
                As[kc + 0][row] = f2tf(v.x);
                As[kc + 1][row] = f2tf(v.y);
                As[kc + 2][row] = f2tf(v.z);
                As[kc + 3][row] = f2tf(v.w);
            }
        }
        {
            int n = tid & 127;
            int f4b = tid >> 7;
            const float* bp = B + (size_t)n * FF_ + k0;
#pragma unroll
            for (int ii = 0; ii < 4; ii++) {
                int f4 = f4b + ii * 2;
                float4 v = *(const float4*)(bp + f4 * 4);
                int kc = f4 * 4;
                Bs[kc + 0][n] = f2tf(v.x);
                Bs[kc + 1][n] = f2tf(v.y);
                Bs[kc + 2][n] = f2tf(v.z);
                Bs[kc + 3][n] = f2tf(v.w);
            }
        }
        __syncthreads();
#pragma unroll
        for (int k8 = 0; k8 < BK; k8 += 8) {
            unsigned a[2][4];
#pragma unroll
            for (int mf = 0; mf < 2; mf++) {
                int r0 = mbase + mf * 16 + grp;
                a[mf][0] = As[k8 + tig][r0];
                a[mf][1] = As[k8 + tig][r0 + 8];
                a[mf][2] = As[k8 + tig + 4][r0];
                a[mf][3] = As[k8 + tig + 4][r0 + 8];
            }
#pragma unroll
            for (int nf = 0; nf < 8; nf++) {
                int n = nbase + nf * 8 + grp;
                unsigned b0 = Bs[k8 + tig][n];
                unsigned b1 = Bs[k8 + tig + 4][n];
                mma8(acc[0][nf], a[0], b0, b1);
                mma8(acc[1][nf], a[1], b0, b1);
            }
        }
        __syncthreads();
    }
#pragma unroll
    for (int mf = 0; mf < 2; mf++) {
        int r0 = block_m + mbase + mf * 16 + grp;
#pragma unroll
        for (int nf = 0; nf < 8; nf++) {
            int col = nbase + nf * 8 + tig * 2;
#pragma unroll
            for (int half = 0; half < 2; half++) {
                int r = r0 + half * 8;
                if (r >= NN_) continue;
                float2 st;
                st.x = tanhf(acc[mf][nf][half * 2 + 0]);
                st.y = tanhf(acc[mf][nf][half * 2 + 1]);
                *(float2*)(C + (size_t)r * HH_ + col) = st;
            }
        }
    }
}

// ---------------- fused het-layer: conv(r=0,1) + attn scores + softmax + combine
// hs for BOTH relations parked in SMEM as fp32 (no register retention, no spills).
// PHASE 0: blockIdx.y = q in 0..7: c=q>>1, li=q&1 (li=0 -> l=1 -> h1; li=1 -> l=0 -> hA)
// PHASE 1: blockIdx.y = c in 0..3, l=1; combined h2 re-stored as tf32 in smem,
//          then fused final GEMM y = [h0|h1|h2] @ Wc^T written straight to yout.
template <int PHASE>
__global__ __launch_bounds__(256)
void het_pair_kernel(const float* __restrict__ agg,
                     const float* __restrict__ convW, const float* __restrict__ convB,
                     const float* __restrict__ attnW1, const float* __restrict__ attnB1,
                     const float* __restrict__ attnW2,
                     const float* __restrict__ din_all,
                     const float* __restrict__ h0b, const float* __restrict__ h1b,
                     const float* __restrict__ Wc,
                     float* __restrict__ h1out, float* __restrict__ hAout,
                     float* __restrict__ yout) {
    constexpr int BK = 32;
    extern __shared__ char smraw[];
    unsigned (*As)[LDSP] = (unsigned(*)[LDSP])(smraw);
    unsigned (*Bs)[LDSP] = (unsigned(*)[LDSP])(smraw + 32 * LDSP * 4);
    float    (*HA)[LDSP] = (float(*)[LDSP])   (smraw + 64 * LDSP * 4);
    float    (*HB)[LDSP] = (float(*)[LDSP])   (smraw + (64 + 128) * LDSP * 4);
    unsigned (*HAu)[LDSP] = (unsigned(*)[LDSP])(smraw + 64 * LDSP * 4);  // alias of HA
    float* s_sm = (float*)(smraw + (64 + 256) * LDSP * 4);   // [2][128]

    const int q = blockIdx.y;
    int c, l;
    float* hout = nullptr;
    if (PHASE == 0) {
        c = q >> 1;
        int li = q & 1;
        l = li ? 0 : 1;
        hout = (li == 0 ? h1out : hAout) + (size_t)c * NH_;
    } else {
        c = q;
        l = 1;
    }
    const int s = c >> 1;

    const int tid  = threadIdx.x;
    const int lane = tid & 31;
    const int warp = tid >> 5;
    const int grp  = lane >> 2;
    const int tig  = lane & 3;
    const int wm   = warp >> 1;
    const int wn   = warp & 1;
    const int mbase = wm * 32;
    const int block_m = blockIdx.x * 128;

    s_sm[tid] = 0.f;   // 256 floats = both relations' score rows

    for (int r = 0; r < 2; r++) {
        float (*HR)[LDSP] = (r == 0) ? HA : HB;
        const int p = c * 2 + r;
        const float* A    = agg + (size_t)p * NH_;
        const float* W    = convW + (size_t)((s * 2 + l) * 2 + r) * HH_ * HH_;
        const float* bias = convB + (size_t)((s * 2 + l) * 2 + r) * HH_;
        const float* W1   = attnW1 + (size_t)(s * 2 + l) * HH_ * QQ_;
        const float* b1   = attnB1 + (size_t)(s * 2 + l) * QQ_;
        const float* w2   = attnW2 + (size_t)(s * 2 + l) * QQ_;
        const float* din  = din_all + p * NN_;

        // ---- stage 1: conv GEMM (K=128, N=128); acc dies at epilogue ----
        {
            float acc[2][8][4];
#pragma unroll
            for (int mf = 0; mf < 2; mf++)
#pragma unroll
                for (int nf = 0; nf < 8; nf++)
#pragma unroll
                    for (int qq = 0; qq < 4; qq++) acc[mf][nf][qq] = 0.f;

            for (int k0 = 0; k0 < HH_; k0 += BK) {
                {
                    int row = tid & 127;
                    int f4b = tid >> 7;
                    int gm = block_m + row;
                    bool ok = (gm < NN_);
                    const float* ap = A + (size_t)gm * HH_ + k0;
#pragma unroll
                    for (int ii = 0; ii < 4; ii++) {
                        int f4 = f4b + ii * 2;
                        float4 v;
                        if (ok) v = *(const float4*)(ap + f4 * 4);
                        else { v.x = v.y = v.z = v.w = 0.f; }
                        int kc = f4 * 4;
                        As[kc + 0][row] = f2tf(v.x);
                        As[kc + 1][row] = f2tf(v.y);
                        As[kc + 2][row] = f2tf(v.z);
                        As[kc + 3][row] = f2tf(v.w);
                    }
                }
                {
                    int f4 = tid & 31;
                    int kb = tid >> 5;
#pragma unroll
                    for (int ii = 0; ii < 4; ii++) {
                        int k = kb + ii * 8;
                        float4 v = *(const float4*)(W + (size_t)(k0 + k) * HH_ + f4 * 4);
                        uint4 w;
                        w.x = f2tf(v.x); w.y = f2tf(v.y); w.z = f2tf(v.z); w.w = f2tf(v.w);
                        *(uint4*)&Bs[k][f4 * 4] = w;
                    }
                }
                __syncthreads();
#pragma unroll
                for (int k8 = 0; k8 < BK; k8 += 8) {
                    unsigned a[2][4];
#pragma unroll
                    for (int mf = 0; mf < 2; mf++) {
                        int r0 = mbase + mf * 16 + grp;
                        a[mf][0] = As[k8 + tig][r0];
                        a[mf][1] = As[k8 + tig][r0 + 8];
                        a[mf][2] = As[k8 + tig + 4][r0];
                        a[mf][3] = As[k8 + tig + 4][r0 + 8];
                    }
#pragma unroll
                    for (int nf = 0; nf < 8; nf++) {
                        int n = wn * 64 + nf * 8 + grp;
                        unsigned b0 = Bs[k8 + tig][n];
                        unsigned b1 = Bs[k8 + tig + 4][n];
                        mma8(acc[0][nf], a[0], b0, b1);
                        mma8(acc[1][nf], a[1], b0, b1);
                    }
                }
                __syncthreads();
            }

            // epilogue: hs = acc*din + bias -> fp32 smem (transposed [col][row])
#pragma unroll
            for (int mf = 0; mf < 2; mf++) {
                int rl0 = mbase + mf * 16 + grp;
#pragma unroll
                for (int nf = 0; nf < 8; nf++) {
                    int col = wn * 64 + nf * 8 + tig * 2;
                    float bc0 = bias[col], bc1 = bias[col + 1];
#pragma unroll
                    for (int half = 0; half < 2; half++) {
                        int rl = rl0 + half * 8;
                        int rg = block_m + rl;
                        float rs = (rg < NN_) ? din[rg] : 0.f;
                        HR[col][rl]     = acc[mf][nf][half * 2 + 0] * rs + bc0;
                        HR[col + 1][rl] = acc[mf][nf][half * 2 + 1] * rs + bc1;
                    }
                }
            }
        }
        __syncthreads();

        // ---- stage 2: t = tanh(hs@W1 + b1); score = t . w2 ----
        float acc2[2][4][4];
#pragma unroll
        for (int mf = 0; mf < 2; mf++)
#pragma unroll
            for (int nf = 0; nf < 4; nf++)
#pragma unroll
                for (int qq = 0; qq < 4; qq++) acc2[mf][nf][qq] = 0.f;

        for (int k0 = 0; k0 < HH_; k0 += BK) {
            {
                int f4 = tid & 15;
                int kb = tid >> 4;
#pragma unroll
                for (int ii = 0; ii < 2; ii++) {
                    int k = kb + ii * 16;
                    float4 v = *(const float4*)(W1 + (size_t)(k0 + k) * QQ_ + f4 * 4);
                    uint4 w;
                    w.x = f2tf(v.x); w.y = f2tf(v.y); w.z = f2tf(v.z); w.w = f2tf(v.w);
                    *(uint4*)&Bs[k][f4 * 4] = w;
                }
            }
            __syncthreads();
#pragma unroll
            for (int k8 = 0; k8 < BK; k8 += 8) {
                unsigned a[2][4];
#pragma unroll
                for (int mf = 0; mf < 2; mf++) {
                    int r0 = mbase + mf * 16 + grp;
                    a[mf][0] = f2tf(HR[k0 + k8 + tig][r0]);
                    a[mf][1] = f2tf(HR[k0 + k8 + tig][r0 + 8]);
                    a[mf][2] = f2tf(HR[k0 + k8 + tig + 4][r0]);
                    a[mf][3] = f2tf(HR[k0 + k8 + tig + 4][r0 + 8]);
                }
#pragma unroll
                for (int nf = 0; nf < 4; nf++) {
                    int n = wn * 32 + nf * 8 + grp;
                    unsigned b0 = Bs[k8 + tig][n];
                    unsigned b1 = Bs[k8 + tig + 4][n];
                    mma8(acc2[0][nf], a[0], b0, b1);
                    mma8(acc2[1][nf], a[1], b0, b1);
                }
            }
            __syncthreads();
        }

        float part[2][2] = {{0.f, 0.f}, {0.f, 0.f}};
#pragma unroll
        for (int mf = 0; mf < 2; mf++)
#pragma unroll
            for (int nf = 0; nf < 4; nf++) {
                int col = wn * 32 + nf * 8 + tig * 2;
                float bc0 = b1[col], bc1 = b1[col + 1];
                float w20 = w2[col], w21 = w2[col + 1];
#pragma unroll
                for (int half = 0; half < 2; half++) {
                    float v0 = tanhf(acc2[mf][nf][half * 2 + 0] + bc0);
                    float v1 = tanhf(acc2[mf][nf][half * 2 + 1] + bc1);
                    part[mf][half] += v0 * w20 + v1 * w21;
                }
            }
#pragma unroll
        for (int o = 1; o <= 2; o <<= 1) {
#pragma unroll
            for (int mf = 0; mf < 2; mf++)
#pragma unroll
                for (int half = 0; half < 2; half++)
                    part[mf][half] += __shfl_xor_sync(0xffffffffu, part[mf][half], o);
        }
        if (tig == 0) {
#pragma unroll
            for (int mf = 0; mf < 2; mf++)
#pragma unroll
                for (int half = 0; half < 2; half++)
                    atomicAdd(&s_sm[r * 128 + mbase + mf * 16 + grp + half * 8],
                              part[mf][half]);
        }
        __syncthreads();   // scores done; As/Bs reusable next r (HR persists)
    }

    // ---- softmax over relations + combine (each thread its own elements) ----
#pragma unroll
    for (int mf = 0; mf < 2; mf++) {
        int rl0 = mbase + mf * 16 + grp;
#pragma unroll
        for (int half = 0; half < 2; half++) {
            int rl = rl0 + half * 8;
            float sv0 = s_sm[rl], sv1 = s_sm[128 + rl];
            float m = fmaxf(sv0, sv1);
            float e0 = expf(sv0 - m), e1 = expf(sv1 - m);
            float a0 = e0 / (e0 + e1), a1 = 1.f - a0;
            int rg = block_m + rl;
#pragma unroll
            for (int nf = 0; nf < 8; nf++) {
                int col = wn * 64 + nf * 8 + tig * 2;
                float v0 = a0 * HA[col][rl]     + a1 * HB[col][rl];
                float v1 = a0 * HA[col + 1][rl] + a1 * HB[col + 1][rl];
                if (PHASE == 0) {
                    if (rg < NN_) {
                        float2 st; st.x = v0; st.y = v1;
                        *(float2*)(hout + (size_t)rg * HH_ + col) = st;
                    }
                } else {
                    HAu[col][rl]     = f2tf(v0);   // h2 tile, transposed tf32
                    HAu[col + 1][rl] = f2tf(v1);
                }
            }
        }
    }

    if (PHASE == 1) {
        // ---- stage 3: y = [h0|h1|h2] @ Wc[s]^T (h2 from smem) ----
        __syncthreads();
        const float* B = Wc + (size_t)s * HH_ * (3 * HH_);
        float acc3[2][8][4];
#pragma unroll
        for (int mf = 0; mf < 2; mf++)
#pragma unroll
            for (int nf = 0; nf < 8; nf++)
#pragma unroll
                for (int qq = 0; qq < 4; qq++) acc3[mf][nf][qq] = 0.f;

        for (int k0 = 0; k0 < 3 * HH_; k0 += BK) {
            int seg = k0 >> 7;
            int kseg = k0 & 127;
            if (seg < 2) {
                const float* A = ((seg == 0) ? h0b : h1b) + (size_t)c * NH_;
                int row = tid & 127;
                int f4b = tid >> 7;
                int gm = block_m + row;
                bool ok = (gm < NN_);
                const float* ap = A + (size_t)gm * HH_ + kseg;
#pragma unroll
                for (int ii = 0; ii < 4; ii++) {
                    int f4 = f4b + ii * 2;
                    float4 v;
                    if (ok) v = *(const float4*)(ap + f4 * 4);
                    else { v.x = v.y = v.z = v.w = 0.f; }
                    int kc = f4 * 4;
                    As[kc + 0][row] = f2tf(v.x);
                    As[kc + 1][row] = f2tf(v.y);
                    As[kc + 2][row] = f2tf(v.z);
                    As[kc + 3][row] = f2tf(v.w);
                }
            }
            {
                int n = tid & 127;
                int f4b = tid >> 7;
                const float* bp = B + (size_t)n * (3 * HH_) + k0;
#pragma unroll
                for (int ii = 0; ii < 4; ii++) {
                    int f4 = f4b + ii * 2;
                    float4 v = *(const float4*)(bp + f4 * 4);
                    int kc = f4 * 4;
                    Bs[kc + 0][n] = f2tf(v.x);
                    Bs[kc + 1][n] = f2tf(v.y);
                    Bs[kc + 2][n] = f2tf(v.z);
                    Bs[kc + 3][n] = f2tf(v.w);
                }
            }
            __syncthreads();
#pragma unroll
            for (int k8 = 0; k8 < BK; k8 += 8) {
                unsigned a[2][4];
#pragma unroll
                for (int mf = 0; mf < 2; mf++) {
                    int r0 = mbase + mf * 16 + grp;
                    if (seg < 2) {
                        a[mf][0] = As[k8 + tig][r0];
                        a[mf][1] = As[k8 + tig][r0 + 8];
                        a[mf][2] = As[k8 + tig + 4][r0];
                        a[mf][3] = As[k8 + tig + 4][r0 + 8];
                    } else {
                        a[mf][0] = HAu[kseg + k8 + tig][r0];
                        a[mf][1] = HAu[kseg + k8 + tig][r0 + 8];
                        a[mf][2] = HAu[kseg + k8 + tig + 4][r0];
                        a[mf][3] = HAu[kseg + k8 + tig + 4][r0 + 8];
                    }
                }
#pragma unroll
                for (int nf = 0; nf < 8; nf++) {
                    int n = wn * 64 + nf * 8 + grp;
                    unsigned b0 = Bs[k8 + tig][n];
                    unsigned b1 = Bs[k8 + tig + 4][n];
                    mma8(acc3[0][nf], a[0], b0, b1);
                    mma8(acc3[1][nf], a[1], b0, b1);
                }
            }
            __syncthreads();
        }
        float* C = yout + (size_t)c * NH_;
#pragma unroll
        for (int mf = 0; mf < 2; mf++) {
            int r0 = block_m + mbase + mf * 16 + grp;
#pragma unroll
            for (int nf = 0; nf < 8; nf++) {
                int col = wn * 64 + nf * 8 + tig * 2;
#pragma unroll
                for (int half = 0; half < 2; half++) {
                    int rr = r0 + half * 8;
                    if (rr >= NN_) continue;
                    float2 st;
                    st.x = acc3[mf][nf][half * 2 + 0];
                    st.y = acc3[mf][nf][half * 2 + 1];
                    *(float2*)(C + (size_t)rr * HH_ + col) = st;
                }
            }
        }
    }
}

// ---------------- host orchestration ----------------------------------------
extern "C" void kernel_launch(void* const* d_in, const int* in_sizes, int n_in,
                              void* d_out, int out_size) {
    const float* x_attr  = (const float*)d_in[0];
    const float* x_stru  = (const float*)d_in[1];
    const int*   e_attr  = (const int*)  d_in[2];
    const int*   e_stru  = (const int*)  d_in[3];
    const float* Wf      = (const float*)d_in[4];   // (2,H,F)
    const float* convW   = (const float*)d_in[5];   // (2,2,2,H,H)
    const float* convB   = (const float*)d_in[6];   // (2,2,2,H)
    const float* attnW1  = (const float*)d_in[7];   // (2,2,H,Q)
    const float* attnB1  = (const float*)d_in[8];   // (2,2,Q)
    const float* attnW2  = (const float*)d_in[9];   // (2,2,Q)
    const float* Wc      = (const float*)d_in[10];  // (2,H,3H)
    float* out = (float*)d_out;

    float *h0, *h1, *hA, *agg, *din, *dout;
    int *cnt_in, *cnt_out, *cursor, *off, *csr;
    cudaGetSymbolAddress((void**)&h0,  g_h0);
    cudaGetSymbolAddress((void**)&h1,  g_h1);
    cudaGetSymbolAddress((void**)&hA,  g_hA);
    cudaGetSymbolAddress((void**)&agg, g_agg);
    cudaGetSymbolAddress((void**)&din,  g_din);
    cudaGetSymbolAddress((void**)&dout, g_dout);
    cudaGetSymbolAddress((void**)&cnt_in,  g_cnt_in);
    cudaGetSymbolAddress((void**)&cnt_out, g_cnt_out);
    cudaGetSymbolAddress((void**)&cursor,  g_cursor);
    cudaGetSymbolAddress((void**)&off, g_off);
    cudaGetSymbolAddress((void**)&csr, g_csr);

    const int TB = 256;
    const int gridM = (NN_ + 127) / 128;
    const int gridWarp = (NN_ + 7) / 8;
    // As+Bs (u32) + HA+HB (fp32) + scores: (64+256)*LDSP*4 + 1KB = ~171 KB
    const int HET_SMEM = (64 + 256) * LDSP * 4 + 256 * 4;
    cudaFuncSetAttribute(het_pair_kernel<0>, cudaFuncAttributeMaxDynamicSharedMemorySize, HET_SMEM);
    cudaFuncSetAttribute(het_pair_kernel<1>, cudaFuncAttributeMaxDynamicSharedMemorySize, HET_SMEM);

    // 1) zero histogram counters
    zero_int_kernel<<<512, TB>>>(cnt_in, 8 * NN_);
    zero_int_kernel<<<512, TB>>>(cnt_out, 8 * NN_);

    // 2) h0 for all 4 runs
    h0_gemm_kernel<<<dim3(gridM, 4), TB>>>(x_attr, x_stru, Wf, h0);

    // 3) CSR build, all 8 pairs batched
    hist_all_kernel<<<dim3(256, 8), TB>>>(e_attr, e_stru, cnt_out, cnt_in);
    deg_all_kernel<<<(8 * NN_ + 255) / 256, TB>>>(cnt_in, cnt_out, din, dout);
    scan_all_kernel<<<8, 1024>>>(cnt_in, off, cursor);
    scatter_all_kernel<<<dim3(256, 8), TB>>>(e_attr, e_stru, cursor, csr);

    // 4) phase A: gather over h0, fused het (8 combos) -> h1, hA
    gather_all_kernel<<<dim3(gridWarp, 8), TB>>>(h0, off, csr, dout, agg);
    het_pair_kernel<0><<<dim3(gridM, 8), TB, HET_SMEM>>>(
        agg, convW, convB, attnW1, attnB1, attnW2, din, h0, h1, Wc, h1, hA, out);

    // 5) phase B: gather over hA, fused het (4) + final concat GEMM -> out
    gather_all_kernel<<<dim3(gridWarp, 8), TB>>>(hA, off, csr, dout, agg);
    het_pair_kernel<1><<<dim3(gridM, 4), TB, HET_SMEM>>>(
        agg, convW, convB, attnW1, attnB1, attnW2, din, h0, h1, Wc, h1, hA, out);
}

// round 8
// speedup vs baseline: 1.3223x; 1.1955x over previous
#include <cuda_runtime.h>
#include <cuda_fp16.h>
#include <math.h>

// Problem constants
#define NN_ 50000
#define EE_ 600000
#define HH_ 128
#define FF_ 256
#define QQ_ 64
#define NH_ (NN_ * HH_)

// ---------------- scratch (device globals; no dynamic allocation) ----------
// all node-feature intermediates stored fp16 (same 10-bit mantissa as tf32)
__device__ __half g_h0 [4 * NH_];
__device__ __half g_h1 [4 * NH_];
__device__ __half g_hA [4 * NH_];
__device__ __half g_h2 [4 * NH_];
__device__ __half g_agg[8 * NH_];
__device__ __half g_hs [16 * NH_];
__device__ float  g_s  [16 * NN_];

__device__ int   g_cnt_in [8 * NN_];
__device__ int   g_cnt_out[8 * NN_];
__device__ int   g_cursor [8 * NN_];
__device__ int   g_off    [8 * (NN_ + 1)];
__device__ int   g_csr    [8 * EE_];
__device__ float g_din    [8 * NN_];
__device__ float g_dout   [8 * NN_];

// ---------------- helpers ---------------------------------------------------
__device__ __forceinline__ const int* edge_ptr_dev(const int* e_attr, const int* e_stru,
                                                   int p, int which) {
    int c = p >> 1, r = p & 1;
    int sign = c >> 1;
    const int* E = (c & 1) ? e_stru : e_attr;
    return E + ((size_t)((sign * 2 + r) * 2 + which)) * EE_;
}

// ---------------- CSR-build kernels (batched over 8 pairs) ------------------
__global__ void zero_int_kernel(int* p, int n) {
    for (int i = blockIdx.x * blockDim.x + threadIdx.x; i < n; i += gridDim.x * blockDim.x)
        p[i] = 0;
}

__global__ void hist_all_kernel(const int* __restrict__ e_attr, const int* __restrict__ e_stru,
                                int* __restrict__ cnt_out, int* __restrict__ cnt_in) {
    int p = blockIdx.y;
    const int* src = edge_ptr_dev(e_attr, e_stru, p, 0);
    const int* dst = edge_ptr_dev(e_attr, e_stru, p, 1);
    int* co = cnt_out + p * NN_;
    int* ci = cnt_in  + p * NN_;
    for (int i = blockIdx.x * blockDim.x + threadIdx.x; i < EE_; i += gridDim.x * blockDim.x) {
        atomicAdd(&co[src[i]], 1);
        atomicAdd(&ci[dst[i]], 1);
    }
}

__global__ void deg_all_kernel(const int* __restrict__ cin, const int* __restrict__ cout,
                               float* __restrict__ din, float* __restrict__ dout) {
    for (int i = blockIdx.x * blockDim.x + threadIdx.x; i < 8 * NN_; i += gridDim.x * blockDim.x) {
        int a = cin[i];  if (a < 1) a = 1;
        int b = cout[i]; if (b < 1) b = 1;
        din [i] = rsqrtf((float)a);
        dout[i] = rsqrtf((float)b);
    }
}

__global__ void scan_all_kernel(const int* __restrict__ cnt_all, int* __restrict__ off_all,
                                int* __restrict__ cur_all) {
    __shared__ int sh[1024];
    const int p = blockIdx.x;
    const int* cnt = cnt_all + p * NN_;
    int* off = off_all + p * (NN_ + 1);
    int* cur = cur_all + p * NN_;
    const int t  = threadIdx.x;
    const int CH = (NN_ + 1023) / 1024;
    const int base = t * CH;
    int s = 0;
    for (int i = 0; i < CH; i++) { int idx = base + i; if (idx < NN_) s += cnt[idx]; }
    sh[t] = s;
    __syncthreads();
    for (int d = 1; d < 1024; d <<= 1) {
        int v = (t >= d) ? sh[t - d] : 0;
        __syncthreads();
        sh[t] += v;
        __syncthreads();
    }
    int run = (t == 0) ? 0 : sh[t - 1];
    for (int i = 0; i < CH; i++) {
        int idx = base + i;
        if (idx < NN_) { off[idx] = run; cur[idx] = run; run += cnt[idx]; }
    }
    if (t == 0) off[NN_] = sh[1023];
}

__global__ void scatter_all_kernel(const int* __restrict__ e_attr, const int* __restrict__ e_stru,
                                   int* __restrict__ cursor, int* __restrict__ csr) {
    int p = blockIdx.y;
    const int* src = edge_ptr_dev(e_attr, e_stru, p, 0);
    const int* dst = edge_ptr_dev(e_attr, e_stru, p, 1);
    int* cu = cursor + p * NN_;
    int* cs = csr + (size_t)p * EE_;
    for (int i = blockIdx.x * blockDim.x + threadIdx.x; i < EE_; i += gridDim.x * blockDim.x) {
        int pos = atomicAdd(&cu[dst[i]], 1);
        cs[pos] = src[i];
    }
}

// ---------------- batched CSR gather (warp per node, fp16 rows) -------------
// per lane: 4 cols = 1 uint2 (4 halves) per edge row; fp32 accumulate
__global__ void gather_all_kernel(const __half* __restrict__ hin_base,
                                  const int* __restrict__ off_all,
                                  const int* __restrict__ csr_all,
                                  const float* __restrict__ dout_all,
                                  __half* __restrict__ agg) {
    int p = blockIdx.y;
    int c = p >> 1;
    const __half* h = hin_base + (size_t)c * NH_;
    const int* off = off_all + p * (NN_ + 1);
    const int* csr = csr_all + (size_t)p * EE_;
    const float* dout = dout_all + p * NN_;
    __half* out = agg + (size_t)p * NH_;

    int warp = (blockIdx.x * blockDim.x + threadIdx.x) >> 5;
    int lane = threadIdx.x & 31;
    if (warp >= NN_) return;
    int b = off[warp], e = off[warp + 1];
    const uint2* h4 = (const uint2*)h;     // 4 halves per uint2; 32 per row
    float ax = 0.f, ay = 0.f, az = 0.f, aw = 0.f;
    int i = b;
    for (; i + 1 < e; i += 2) {
        int s0 = csr[i], s1 = csr[i + 1];
        float w0 = dout[s0], w1 = dout[s1];
        uint2 u0 = h4[(size_t)s0 * 32 + lane];
        uint2 u1 = h4[(size_t)s1 * 32 + lane];
        float2 a0 = __half22float2(*(__half2*)&u0.x);
        float2 b0 = __half22float2(*(__half2*)&u0.y);
        float2 a1 = __half22float2(*(__half2*)&u1.x);
        float2 b1 = __half22float2(*(__half2*)&u1.y);
        ax += w0 * a0.x + w1 * a1.x;
        ay += w0 * a0.y + w1 * a1.y;
        az += w0 * b0.x + w1 * b1.x;
        aw += w0 * b0.y + w1 * b1.y;
    }
    if (i < e) {
        int s0 = csr[i];
        float w0 = dout[s0];
        uint2 u0 = h4[(size_t)s0 * 32 + lane];
        float2 a0 = __half22float2(*(__half2*)&u0.x);
        float2 b0 = __half22float2(*(__half2*)&u0.y);
        ax += w0 * a0.x; ay += w0 * a0.y; az += w0 * b0.x; aw += w0 * b0.y;
    }
    uint2 st;
    *(__half2*)&st.x = __floats2half2_rn(ax, ay);
    *(__half2*)&st.y = __floats2half2_rn(az, aw);
    ((uint2*)out)[(size_t)warp * 32 + lane] = st;
}

// ---------------- tf32 helpers ----------------------------------------------
__device__ __forceinline__ unsigned f2tf(float f) {
    unsigned u;
    asm("cvt.rna.tf32.f32 %0, %1;" : "=r"(u) : "f"(f));
    return u;
}

__device__ __forceinline__ void mma8(float* c, const unsigned* a, unsigned b0, unsigned b1) {
    asm volatile(
        "mma.sync.aligned.m16n8k8.row.col.f32.tf32.tf32.f32 "
        "{%0,%1,%2,%3},{%4,%5,%6,%7},{%8,%9},{%0,%1,%2,%3};"
        : "+f"(c[0]), "+f"(c[1]), "+f"(c[2]), "+f"(c[3])
        : "r"(a[0]), "r"(a[1]), "r"(a[2]), "r"(a[3]), "r"(b0), "r"(b1));
}

#define LDSP 136    // pad 8: bank = 8*tig + grp -> conflict-free fragment reads

// fp16 A-tile loader: 128 rows x 32 halves -> As[k][row] tf32
// row = tid&127, hb = tid>>7 covers halves [hb*16, hb*16+16)
template <int LDS>
__device__ __forceinline__ void load_A_fp16(unsigned (*As)[LDS], const __half* A,
                                            int block_m, int k0, int tid, int M) {
    int row = tid & 127;
    int hb = tid >> 7;
    int gm = block_m + row;
    bool ok = (gm < M);
    const __half* ap = A + (size_t)gm * HH_ + k0 + hb * 16;
    uint4 v0, v1;
    if (ok) { v0 = *(const uint4*)ap; v1 = *(const uint4*)(ap + 8); }
    else { v0 = make_uint4(0, 0, 0, 0); v1 = make_uint4(0, 0, 0, 0); }
    int kb = hb * 16;
#pragma unroll
    for (int j = 0; j < 4; j++) {
        float2 fa = __half22float2(((const __half2*)&v0)[j]);
        As[kb + j * 2 + 0][row] = f2tf(fa.x);
        As[kb + j * 2 + 1][row] = f2tf(fa.y);
        float2 fb = __half22float2(((const __half2*)&v1)[j]);
        As[kb + 8 + j * 2 + 0][row] = f2tf(fb.x);
        As[kb + 8 + j * 2 + 1][row] = f2tf(fb.y);
    }
}

// ---------------- h0 GEMM: h0 = tanh(x @ Wf[s]^T) -> fp16, batched over 4 ---
__global__ __launch_bounds__(256)
void h0_gemm_kernel(const float* __restrict__ x_attr, const float* __restrict__ x_stru,
                    const float* __restrict__ Wf, __half* __restrict__ h0b) {
    constexpr int BK = 32;
    __shared__ unsigned As[BK][LDSP];
    __shared__ unsigned Bs[BK][LDSP];

    const int c = blockIdx.y;
    const int s = c >> 1;
    const float* A = (c & 1) ? x_stru : x_attr;
    const float* B = Wf + (size_t)s * HH_ * FF_;
    __half* C = h0b + (size_t)c * NH_;

    const int tid  = threadIdx.x;
    const int lane = tid & 31;
    const int warp = tid >> 5;
    const int grp  = lane >> 2;
    const int tig  = lane & 3;
    const int wm   = warp >> 1;
    const int wn   = warp & 1;
    const int mbase = wm * 32;
    const int nbase = wn * 64;
    const int block_m = blockIdx.x * 128;

    float acc[2][8][4];
#pragma unroll
    for (int mf = 0; mf < 2; mf++)
#pragma unroll
        for (int nf = 0; nf < 8; nf++)
#pragma unroll
            for (int q = 0; q < 4; q++) acc[mf][nf][q] = 0.f;

    for (int k0 = 0; k0 < FF_; k0 += BK) {
        {
            int row = tid & 127;
            int f4b = tid >> 7;
            int gm = block_m + row;
            bool ok = (gm < NN_);
            const float* ap = A + (size_t)gm * FF_ + k0;
#pragma unroll
            for (int ii = 0; ii < 4; ii++) {
                int f4 = f4b + ii * 2;
                float4 v;
                if (ok) v = *(const float4*)(ap + f4 * 4);
                else { v.x = v.y = v.z = v.w = 0.f; }
                int kc = f4 * 4;
                As[kc + 0][row] = f2tf(v.x);
                As[kc + 1][row] = f2tf(v.y);
                As[kc + 2][row] = f2tf(v.z);
                As[kc + 3][row] = f2tf(v.w);
            }
        }
        {
            int n = tid & 127;
            int f4b = tid >> 7;
            const float* bp = B + (size_t)n * FF_ + k0;
#pragma unroll
            for (int ii = 0; ii < 4; ii++) {
                int f4 = f4b + ii * 2;
                float4 v = *(const float4*)(bp + f4 * 4);
                int kc = f4 * 4;
                Bs[kc + 0][n] = f2tf(v.x);
                Bs[kc + 1][n] = f2tf(v.y);
                Bs[kc + 2][n] = f2tf(v.z);
                Bs[kc + 3][n] = f2tf(v.w);
            }
        }
        __syncthreads();
#pragma unroll
        for (int k8 = 0; k8 < BK; k8 += 8) {
            unsigned a[2][4];
#pragma unroll
            for (int mf = 0; mf < 2; mf++) {
                int r0 = mbase + mf * 16 + grp;
                a[mf][0] = As[k8 + tig][r0];
                a[mf][1] = As[k8 + tig][r0 + 8];
                a[mf][2] = As[k8 + tig + 4][r0];
                a[mf][3] = As[k8 + tig + 4][r0 + 8];
            }
#pragma unroll
            for (int nf = 0; nf < 8; nf++) {
                int n = nbase + nf * 8 + grp;
                unsigned b0 = Bs[k8 + tig][n];
                unsigned b1 = Bs[k8 + tig + 4][n];
                mma8(acc[0][nf], a[0], b0, b1);
                mma8(acc[1][nf], a[1], b0, b1);
            }
        }
        __syncthreads();
    }
#pragma unroll
    for (int mf = 0; mf < 2; mf++) {
        int r0 = block_m + mbase + mf * 16 + grp;
#pragma unroll
        for (int nf = 0; nf < 8; nf++) {
            int col = nbase + nf * 8 + tig * 2;
#pragma unroll
            for (int half = 0; half < 2; half++) {
                int r = r0 + half * 8;
                if (r >= NN_) continue;
                *(__half2*)(C + (size_t)r * HH_ + col) =
                    __floats2half2_rn(tanhf(acc[mf][nf][half * 2 + 0]),
                                      tanhf(acc[mf][nf][half * 2 + 1]));
            }
        }
    }
}

// ---------------- batched fused conv GEMM + attention score -----------------
// A (agg) fp16; hs out fp16; scores fp32.
// PHASE 0: blockIdx.y = q in 0..15: c=q>>2, li=(q>>1)&1 (li=0 -> l=1, li=1 -> l=0), r=q&1
// PHASE 1: blockIdx.y = q in 0..7:  c=q>>1, r=q&1, l=1
template <int PHASE>
__global__ __launch_bounds__(256)
void het_all_kernel(const __half* __restrict__ agg,
                    const float* __restrict__ convW, const float* __restrict__ convB,
                    const float* __restrict__ attnW1, const float* __restrict__ attnB1,
                    const float* __restrict__ attnW2,
                    const float* __restrict__ din_all,
                    __half* __restrict__ hs_all, float* __restrict__ s_all) {
    constexpr int BK = 32;
    extern __shared__ char smraw[];
    unsigned (*As)[LDSP]  = (unsigned(*)[LDSP])(smraw);
    unsigned (*Bs)[LDSP]  = (unsigned(*)[LDSP])(smraw + 32 * LDSP * 4);
    unsigned (*HSs)[LDSP] = (unsigned(*)[LDSP])(smraw + 64 * LDSP * 4);
    float* s_sm = (float*)(smraw + (64 + 128) * LDSP * 4);

    const int q = blockIdx.y;
    int c, l, r;
    if (PHASE == 0) { c = q >> 2; l = ((q >> 1) & 1) ? 0 : 1; r = q & 1; }
    else            { c = q >> 1; l = 1; r = q & 1; }
    const int s = c >> 1;
    const int p = c * 2 + r;

    const __half* A   = agg + (size_t)p * NH_;
    const float* W    = convW + (size_t)((s * 2 + l) * 2 + r) * HH_ * HH_;
    const float* bias = convB + (size_t)((s * 2 + l) * 2 + r) * HH_;
    const float* W1   = attnW1 + (size_t)(s * 2 + l) * HH_ * QQ_;
    const float* b1   = attnB1 + (size_t)(s * 2 + l) * QQ_;
    const float* w2   = attnW2 + (size_t)(s * 2 + l) * QQ_;
    const float* din  = din_all + p * NN_;
    __half* hs_out = hs_all + (size_t)q * NH_;
    float* s_out  = s_all + (size_t)q * NN_;

    const int tid  = threadIdx.x;
    const int lane = tid & 31;
    const int warp = tid >> 5;
    const int grp  = lane >> 2;
    const int tig  = lane & 3;
    const int wm   = warp >> 1;
    const int wn   = warp & 1;
    const int mbase = wm * 32;
    const int block_m = blockIdx.x * 128;

    if (tid < 128) s_sm[tid] = 0.f;

    // ---------------- stage 1: conv GEMM (K=128, BN=128) ----------------
    float acc[2][8][4];
#pragma unroll
    for (int mf = 0; mf < 2; mf++)
#pragma unroll
        for (int nf = 0; nf < 8; nf++)
#pragma unroll
            for (int qq = 0; qq < 4; qq++) acc[mf][nf][qq] = 0.f;

    for (int k0 = 0; k0 < HH_; k0 += BK) {
        load_A_fp16<LDSP>(As, A, block_m, k0, tid, NN_);
        {
            int f4 = tid & 31;
            int kb = tid >> 5;
#pragma unroll
            for (int ii = 0; ii < 4; ii++) {
                int k = kb + ii * 8;
                float4 v = *(const float4*)(W + (size_t)(k0 + k) * HH_ + f4 * 4);
                uint4 w;
                w.x = f2tf(v.x); w.y = f2tf(v.y); w.z = f2tf(v.z); w.w = f2tf(v.w);
                *(uint4*)&Bs[k][f4 * 4] = w;
            }
        }
        __syncthreads();
#pragma unroll
        for (int k8 = 0; k8 < BK; k8 += 8) {
            unsigned a[2][4];
#pragma unroll
            for (int mf = 0; mf < 2; mf++) {
                int r0 = mbase + mf * 16 + grp;
                a[mf][0] = As[k8 + tig][r0];
                a[mf][1] = As[k8 + tig][r0 + 8];
                a[mf][2] = As[k8 + tig + 4][r0];
                a[mf][3] = As[k8 + tig + 4][r0 + 8];
            }
#pragma unroll
            for (int nf = 0; nf < 8; nf++) {
                int n = wn * 64 + nf * 8 + grp;
                unsigned b0 = Bs[k8 + tig][n];
                unsigned b1 = Bs[k8 + tig + 4][n];
                mma8(acc[0][nf], a[0], b0, b1);
                mma8(acc[1][nf], a[1], b0, b1);
            }
        }
        __syncthreads();
    }

    // stage-1 epilogue: hs = acc*din + b; fp16 global write + transposed tf32 smem
#pragma unroll
    for (int mf = 0; mf < 2; mf++) {
        int rl0 = mbase + mf * 16 + grp;
#pragma unroll
        for (int nf = 0; nf < 8; nf++) {
            int col = wn * 64 + nf * 8 + tig * 2;
            float bc0 = bias[col], bc1 = bias[col + 1];
#pragma unroll
            for (int half = 0; half < 2; half++) {
                int rl = rl0 + half * 8;
                int rg = block_m + rl;
                float rs = (rg < NN_) ? din[rg] : 0.f;
                float v0 = acc[mf][nf][half * 2 + 0] * rs + bc0;
                float v1 = acc[mf][nf][half * 2 + 1] * rs + bc1;
                HSs[col][rl]     = f2tf(v0);
                HSs[col + 1][rl] = f2tf(v1);
                if (rg < NN_)
                    *(__half2*)(hs_out + (size_t)rg * HH_ + col) = __floats2half2_rn(v0, v1);
            }
        }
    }
    __syncthreads();

    // ---------------- stage 2: t = tanh(hs@W1 + b1); s = t.w2 ----------------
    float acc2[2][4][4];
#pragma unroll
    for (int mf = 0; mf < 2; mf++)
#pragma unroll
        for (int nf = 0; nf < 4; nf++)
#pragma unroll
            for (int qq = 0; qq < 4; qq++) acc2[mf][nf][qq] = 0.f;

    for (int k0 = 0; k0 < HH_; k0 += BK) {
        {
            int f4 = tid & 15;
            int kb = tid >> 4;
#pragma unroll
            for (int ii = 0; ii < 2; ii++) {
                int k = kb + ii * 16;
                float4 v = *(const float4*)(W1 + (size_t)(k0 + k) * QQ_ + f4 * 4);
                uint4 w;
                w.x = f2tf(v.x); w.y = f2tf(v.y); w.z = f2tf(v.z); w.w = f2tf(v.w);
                *(uint4*)&Bs[k][f4 * 4] = w;
            }
        }
        __syncthreads();
#pragma unroll
        for (int k8 = 0; k8 < BK; k8 += 8) {
            unsigned a[2][4];
#pragma unroll
            for (int mf = 0; mf < 2; mf++) {
                int r0 = mbase + mf * 16 + grp;
                a[mf][0] = HSs[k0 + k8 + tig][r0];
                a[mf][1] = HSs[k0 + k8 + tig][r0 + 8];
                a[mf][2] = HSs[k0 + k8 + tig + 4][r0];
                a[mf][3] = HSs[k0 + k8 + tig + 4][r0 + 8];
            }
#pragma unroll
            for (int nf = 0; nf < 4; nf++) {
                int n = wn * 32 + nf * 8 + grp;
                unsigned b0 = Bs[k8 + tig][n];
                unsigned b1 = Bs[k8 + tig + 4][n];
                mma8(acc2[0][nf], a[0], b0, b1);
                mma8(acc2[1][nf], a[1], b0, b1);
            }
        }
        __syncthreads();
    }

    float part[2][2] = {{0.f, 0.f}, {0.f, 0.f}};
#pragma unroll
    for (int mf = 0; mf < 2; mf++)
#pragma unroll
        for (int nf = 0; nf < 4; nf++) {
            int col = wn * 32 + nf * 8 + tig * 2;
            float bc0 = b1[col], bc1 = b1[col + 1];
            float w20 = w2[col], w21 = w2[col + 1];
#pragma unroll
            for (int half = 0; half < 2; half++) {
                float v0 = tanhf(acc2[mf][nf][half * 2 + 0] + bc0);
                float v1 = tanhf(acc2[mf][nf][half * 2 + 1] + bc1);
                part[mf][half] += v0 * w20 + v1 * w21;
            }
        }
#pragma unroll
    for (int o = 1; o <= 2; o <<= 1) {
#pragma unroll
        for (int mf = 0; mf < 2; mf++)
#pragma unroll
            for (int half = 0; half < 2; half++)
                part[mf][half] += __shfl_xor_sync(0xffffffffu, part[mf][half], o);
    }
    if (tig == 0) {
#pragma unroll
        for (int mf = 0; mf < 2; mf++)
#pragma unroll
            for (int half = 0; half < 2; half++)
                atomicAdd(&s_sm[mbase + mf * 16 + grp + half * 8], part[mf][half]);
    }
    __syncthreads();
    if (tid < 128) {
        int rg = block_m + tid;
        if (rg < NN_) s_out[rg] = s_sm[tid];
    }
}

// ---------------- batched attention combine (fp16 hs/out) -------------------
// PHASE 0: blockIdx.y = u in 0..7: c=u>>1, li=u&1; hs pair at q0=c*4+li*2;
//          out = (li==0 ? h1 : hA) + c*NH_
// PHASE 1: blockIdx.y = c in 0..3; hs pair at q0=c*2; out = h2 + c*NH_
template <int PHASE>
__global__ void combine_all_kernel(const __half* __restrict__ hs_all,
                                   const float* __restrict__ s_all,
                                   __half* __restrict__ h1b, __half* __restrict__ hAb,
                                   __half* __restrict__ h2b) {
    const int u = blockIdx.y;
    int q0, c;
    __half* outb;
    if (PHASE == 0) {
        c = u >> 1;
        int li = u & 1;
        q0 = c * 4 + li * 2;
        outb = (li == 0 ? h1b : hAb);
    } else {
        c = u;
        q0 = c * 2;
        outb = h2b;
    }
    const __half* hs0 = hs_all + (size_t)q0 * NH_;
    const __half* hs1 = hs_all + (size_t)(q0 + 1) * NH_;
    const float* s0 = s_all + (size_t)q0 * NN_;
    const float* s1 = s_all + (size_t)(q0 + 1) * NN_;
    __half* out = outb + (size_t)c * NH_;

    int warp = (blockIdx.x * blockDim.x + threadIdx.x) >> 5;
    int lane = threadIdx.x & 31;
    if (warp >= NN_) return;
    float sv0 = s0[warp], sv1 = s1[warp];
    float m = fmaxf(sv0, sv1);
    float e0 = expf(sv0 - m), e1 = expf(sv1 - m);
    float a0 = e0 / (e0 + e1), a1 = 1.f - a0;
    uint2 u0 = ((const uint2*)(hs0 + (size_t)warp * HH_))[lane];
    uint2 u1 = ((const uint2*)(hs1 + (size_t)warp * HH_))[lane];
    float2 f0a = __half22float2(*(__half2*)&u0.x);
    float2 f0b = __half22float2(*(__half2*)&u0.y);
    float2 f1a = __half22float2(*(__half2*)&u1.x);
    float2 f1b = __half22float2(*(__half2*)&u1.y);
    uint2 st;
    *(__half2*)&st.x = __floats2half2_rn(a0 * f0a.x + a1 * f1a.x, a0 * f0a.y + a1 * f1a.y);
    *(__half2*)&st.y = __floats2half2_rn(a0 * f0b.x + a1 * f1b.x, a0 * f0b.y + a1 * f1b.y);
    ((uint2*)(out + (size_t)warp * HH_))[lane] = st;
}

// ---------------- final GEMM: y = [h0|h1|h2](fp16) @ Wc^T -> fp32 out -------
__global__ __launch_bounds__(256)
void final_gemm_kernel(const __half* __restrict__ h0b, const __half* __restrict__ h1b,
                       const __half* __restrict__ h2b, const float* __restrict__ Wc,
                       float* __restrict__ Cout) {
    constexpr int BK = 32;
    __shared__ unsigned As[BK][LDSP];
    __shared__ unsigned Bs[BK][LDSP];

    const int c = blockIdx.y;
    const int s = c >> 1;
    const float* B = Wc + (size_t)s * HH_ * (3 * HH_);
    float* C = Cout + (size_t)c * NH_;

    const int tid  = threadIdx.x;
    const int lane = tid & 31;
    const int warp = tid >> 5;
    const int grp  = lane >> 2;
    const int tig  = lane & 3;
    const int wm   = warp >> 1;
    const int wn   = warp & 1;
    const int mbase = wm * 32;
    const int nbase = wn * 64;
    const int block_m = blockIdx.x * 128;

    float acc[2][8][4];
#pragma unroll
    for (int mf = 0; mf < 2; mf++)
#pragma unroll
        for (int nf = 0; nf < 8; nf++)
#pragma unroll
            for (int q = 0; q < 4; q++) acc[mf][nf][q] = 0.f;

    for (int k0 = 0; k0 < 3 * HH_; k0 += BK) {
        int seg = k0 >> 7;
        int kseg = k0 & 127;
        const __half* A = ((seg == 0) ? h0b : ((seg == 1) ? h1b : h2b)) + (size_t)c * NH_;
        load_A_fp16<LDSP>(As, A, block_m, kseg, tid, NN_);
        {
            int n = tid & 127;
            int f4b = tid >> 7;
            const float* bp = B + (size_t)n * (3 * HH_) + k0;
#pragma unroll
            for (int ii = 0; ii < 4; ii++) {
                int f4 = f4b + ii * 2;
                float4 v = *(const float4*)(bp + f4 * 4);
                int kc = f4 * 4;
                Bs[kc + 0][n] = f2tf(v.x);
                Bs[kc + 1][n] = f2tf(v.y);
                Bs[kc + 2][n] = f2tf(v.z);
                Bs[kc + 3][n] = f2tf(v.w);
            }
        }
        __syncthreads();
#pragma unroll
        for (int k8 = 0; k8 < BK; k8 += 8) {
            unsigned a[2][4];
#pragma unroll
            for (int mf = 0; mf < 2; mf++) {
                int r0 = mbase + mf * 16 + grp;
                a[mf][0] = As[k8 + tig][r0];
                a[mf][1] = As[k8 + tig][r0 + 8];
                a[mf][2] = As[k8 + tig + 4][r0];
                a[mf][3] = As[k8 + tig + 4][r0 + 8];
            }
#pragma unroll
            for (int nf = 0; nf < 8; nf++) {
                int n = nbase + nf * 8 + grp;
                unsigned b0 = Bs[k8 + tig][n];
                unsigned b1 = Bs[k8 + tig + 4][n];
                mma8(acc[0][nf], a[0], b0, b1);
                mma8(acc[1][nf], a[1], b0, b1);
            }
        }
        __syncthreads();
    }
#pragma unroll
    for (int mf = 0; mf < 2; mf++) {
        int r0 = block_m + mbase + mf * 16 + grp;
#pragma unroll
        for (int nf = 0; nf < 8; nf++) {
            int col = nbase + nf * 8 + tig * 2;
#pragma unroll
            for (int half = 0; half < 2; half++) {
                int r = r0 + half * 8;
                if (r >= NN_) continue;
                float2 st;
                st.x = acc[mf][nf][half * 2 + 0];
                st.y = acc[mf][nf][half * 2 + 1];
                *(float2*)(C + (size_t)r * HH_ + col) = st;
            }
        }
    }
}

// ---------------- host orchestration ----------------------------------------
extern "C" void kernel_launch(void* const* d_in, const int* in_sizes, int n_in,
                              void* d_out, int out_size) {
    const float* x_attr  = (const float*)d_in[0];
    const float* x_stru  = (const float*)d_in[1];
    const int*   e_attr  = (const int*)  d_in[2];
    const int*   e_stru  = (const int*)  d_in[3];
    const float* Wf      = (const float*)d_in[4];   // (2,H,F)
    const float* convW   = (const float*)d_in[5];   // (2,2,2,H,H)
    const float* convB   = (const float*)d_in[6];   // (2,2,2,H)
    const float* attnW1  = (const float*)d_in[7];   // (2,2,H,Q)
    const float* attnB1  = (const float*)d_in[8];   // (2,2,Q)
    const float* attnW2  = (const float*)d_in[9];   // (2,2,Q)
    const float* Wc      = (const float*)d_in[10];  // (2,H,3H)
    float* out = (float*)d_out;

    __half *h0, *h1, *hA, *h2, *agg, *hs;
    float *sb, *din, *dout;
    int *cnt_in, *cnt_out, *cursor, *off, *csr;
    cudaGetSymbolAddress((void**)&h0,  g_h0);
    cudaGetSymbolAddress((void**)&h1,  g_h1);
    cudaGetSymbolAddress((void**)&hA,  g_hA);
    cudaGetSymbolAddress((void**)&h2,  g_h2);
    cudaGetSymbolAddress((void**)&agg, g_agg);
    cudaGetSymbolAddress((void**)&hs,  g_hs);
    cudaGetSymbolAddress((void**)&sb,  g_s);
    cudaGetSymbolAddress((void**)&din,  g_din);
    cudaGetSymbolAddress((void**)&dout, g_dout);
    cudaGetSymbolAddress((void**)&cnt_in,  g_cnt_in);
    cudaGetSymbolAddress((void**)&cnt_out, g_cnt_out);
    cudaGetSymbolAddress((void**)&cursor,  g_cursor);
    cudaGetSymbolAddress((void**)&off, g_off);
    cudaGetSymbolAddress((void**)&csr, g_csr);

    const int TB = 256;
    const int gridM = (NN_ + 127) / 128;
    const int gridWarp = (NN_ + 7) / 8;
    const int HET_SMEM = (64 + 128) * LDSP * 4 + 512;   // ~102.5 KB -> 2 blocks/SM
    cudaFuncSetAttribute(het_all_kernel<0>, cudaFuncAttributeMaxDynamicSharedMemorySize, HET_SMEM);
    cudaFuncSetAttribute(het_all_kernel<1>, cudaFuncAttributeMaxDynamicSharedMemorySize, HET_SMEM);

    // 1) zero histogram counters
    zero_int_kernel<<<512, TB>>>(cnt_in, 8 * NN_);
    zero_int_kernel<<<512, TB>>>(cnt_out, 8 * NN_);

    // 2) h0 for all 4 runs (fp16 out)
    h0_gemm_kernel<<<dim3(gridM, 4), TB>>>(x_attr, x_stru, Wf, h0);

    // 3) CSR build, all 8 pairs batched
    hist_all_kernel<<<dim3(256, 8), TB>>>(e_attr, e_stru, cnt_out, cnt_in);
    deg_all_kernel<<<(8 * NN_ + 255) / 256, TB>>>(cnt_in, cnt_out, din, dout);
    scan_all_kernel<<<8, 1024>>>(cnt_in, off, cursor);
    scatter_all_kernel<<<dim3(256, 8), TB>>>(e_attr, e_stru, cursor, csr);

    // 4) phase A: gather over h0 (8 pairs), het (16 combos), combine (8)
    gather_all_kernel<<<dim3(gridWarp, 8), TB>>>(h0, off, csr, dout, agg);
    het_all_kernel<0><<<dim3(gridM, 16), TB, HET_SMEM>>>(
        agg, convW, convB, attnW1, attnB1, attnW2, din, hs, sb);
    combine_all_kernel<0><<<dim3(gridWarp, 8), TB>>>(hs, sb, h1, hA, h2);

    // 5) phase B: gather over hA (8), het (8), combine (4)
    gather_all_kernel<<<dim3(gridWarp, 8), TB>>>(hA, off, csr, dout, agg);
    het_all_kernel<1><<<dim3(gridM, 8), TB, HET_SMEM>>>(
        agg, convW, convB, attnW1, attnB1, attnW2, din, hs, sb);
    combine_all_kernel<1><<<dim3(gridWarp, 4), TB>>>(hs, sb, h1, hA, h2);

    // 6) final: y = [h0|h1|h2] @ Wc^T for all 4 runs (fp32 out)
    final_gemm_kernel<<<dim3(gridM, 4), TB>>>(h0, h1, h2, Wc, out);
}

// round 9
// speedup vs baseline: 1.5414x; 1.1657x over previous
#include <cuda_runtime.h>
#include <cuda_fp16.h>
#include <math.h>

// Problem constants
#define NN_ 50000
#define EE_ 600000
#define HH_ 128
#define FF_ 256
#define QQ_ 64
#define NH_ (NN_ * HH_)

// ---------------- scratch (device globals; no dynamic allocation) ----------
__device__ __half g_h0 [4 * NH_];
__device__ __half g_h1 [4 * NH_];
__device__ __half g_hA [4 * NH_];
__device__ __half g_h2 [4 * NH_];
__device__ __half g_agg[8 * NH_];
__device__ __half g_hs [16 * NH_];
__device__ float  g_s  [16 * NN_];

// fp16 weight copies, [n][k] layout (transposed where needed by prep kernel)
__device__ __half g_wf16 [2 * HH_ * FF_];        // [s][n=128][k=256]
__device__ __half g_cw16 [8 * HH_ * HH_];        // [m][n=128][k=128]
__device__ __half g_w116 [4 * QQ_ * HH_];        // [m][n=64][k=128]
__device__ __half g_wc16 [2 * HH_ * 3 * HH_];    // [s][n=128][k=384]

__device__ int   g_cnt_in [8 * NN_];
__device__ int   g_cnt_out[8 * NN_];
__device__ int   g_cursor [8 * NN_];
__device__ int   g_off    [8 * (NN_ + 1)];
__device__ int   g_csr    [8 * EE_];
__device__ float g_din    [8 * NN_];
__device__ float g_dout   [8 * NN_];

// ---------------- helpers ---------------------------------------------------
__device__ __forceinline__ const int* edge_ptr_dev(const int* e_attr, const int* e_stru,
                                                   int p, int which) {
    int c = p >> 1, r = p & 1;
    int sign = c >> 1;
    const int* E = (c & 1) ? e_stru : e_attr;
    return E + ((size_t)((sign * 2 + r) * 2 + which)) * EE_;
}

// ---------------- weight prep: fp32 -> fp16, [n][k] layouts -----------------
__global__ void prep_weights_kernel(const float* __restrict__ Wf, const float* __restrict__ convW,
                                    const float* __restrict__ attnW1, const float* __restrict__ Wc,
                                    __half* __restrict__ wf16, __half* __restrict__ cw16,
                                    __half* __restrict__ w116, __half* __restrict__ wc16) {
    const int NWF = 2 * HH_ * FF_;
    const int NCW = 8 * HH_ * HH_;
    const int NW1 = 4 * QQ_ * HH_;
    const int NWC = 2 * HH_ * 3 * HH_;
    for (int i = blockIdx.x * blockDim.x + threadIdx.x;
         i < NWF + NCW + NW1 + NWC; i += gridDim.x * blockDim.x) {
        if (i < NWF) {
            wf16[i] = __float2half_rn(Wf[i]);                       // already [s][n][k]
        } else if (i < NWF + NCW) {
            int j = i - NWF;
            int m = j / (HH_ * HH_), t = j % (HH_ * HH_);
            int n = t / HH_, k = t % HH_;
            cw16[j] = __float2half_rn(convW[m * HH_ * HH_ + k * HH_ + n]);   // transpose
        } else if (i < NWF + NCW + NW1) {
            int j = i - NWF - NCW;
            int m = j / (QQ_ * HH_), t = j % (QQ_ * HH_);
            int n = t / HH_, k = t % HH_;
            w116[j] = __float2half_rn(attnW1[m * HH_ * QQ_ + k * QQ_ + n]);  // transpose
        } else {
            int j = i - NWF - NCW - NW1;
            wc16[j] = __float2half_rn(Wc[j]);                       // already [s][n][k]
        }
    }
}

// ---------------- CSR-build kernels (batched over 8 pairs) ------------------
__global__ void zero_int_kernel(int* p, int n) {
    for (int i = blockIdx.x * blockDim.x + threadIdx.x; i < n; i += gridDim.x * blockDim.x)
        p[i] = 0;
}

__global__ void hist_all_kernel(const int* __restrict__ e_attr, const int* __restrict__ e_stru,
                                int* __restrict__ cnt_out, int* __restrict__ cnt_in) {
    int p = blockIdx.y;
    const int* src = edge_ptr_dev(e_attr, e_stru, p, 0);
    const int* dst = edge_ptr_dev(e_attr, e_stru, p, 1);
    int* co = cnt_out + p * NN_;
    int* ci = cnt_in  + p * NN_;
    for (int i = blockIdx.x * blockDim.x + threadIdx.x; i < EE_; i += gridDim.x * blockDim.x) {
        atomicAdd(&co[src[i]], 1);
        atomicAdd(&ci[dst[i]], 1);
    }
}

__global__ void deg_all_kernel(const int* __restrict__ cin, const int* __restrict__ cout,
                               float* __restrict__ din, float* __restrict__ dout) {
    for (int i = blockIdx.x * blockDim.x + threadIdx.x; i < 8 * NN_; i += gridDim.x * blockDim.x) {
        int a = cin[i];  if (a < 1) a = 1;
        int b = cout[i]; if (b < 1) b = 1;
        din [i] = rsqrtf((float)a);
        dout[i] = rsqrtf((float)b);
    }
}

__global__ void scan_all_kernel(const int* __restrict__ cnt_all, int* __restrict__ off_all,
                                int* __restrict__ cur_all) {
    __shared__ int sh[1024];
    const int p = blockIdx.x;
    const int* cnt = cnt_all + p * NN_;
    int* off = off_all + p * (NN_ + 1);
    int* cur = cur_all + p * NN_;
    const int t  = threadIdx.x;
    const int CH = (NN_ + 1023) / 1024;
    const int base = t * CH;
    int s = 0;
    for (int i = 0; i < CH; i++) { int idx = base + i; if (idx < NN_) s += cnt[idx]; }
    sh[t] = s;
    __syncthreads();
    for (int d = 1; d < 1024; d <<= 1) {
        int v = (t >= d) ? sh[t - d] : 0;
        __syncthreads();
        sh[t] += v;
        __syncthreads();
    }
    int run = (t == 0) ? 0 : sh[t - 1];
    for (int i = 0; i < CH; i++) {
        int idx = base + i;
        if (idx < NN_) { off[idx] = run; cur[idx] = run; run += cnt[idx]; }
    }
    if (t == 0) off[NN_] = sh[1023];
}

__global__ void scatter_all_kernel(const int* __restrict__ e_attr, const int* __restrict__ e_stru,
                                   int* __restrict__ cursor, int* __restrict__ csr) {
    int p = blockIdx.y;
    const int* src = edge_ptr_dev(e_attr, e_stru, p, 0);
    const int* dst = edge_ptr_dev(e_attr, e_stru, p, 1);
    int* cu = cursor + p * NN_;
    int* cs = csr + (size_t)p * EE_;
    for (int i = blockIdx.x * blockDim.x + threadIdx.x; i < EE_; i += gridDim.x * blockDim.x) {
        int pos = atomicAdd(&cu[dst[i]], 1);
        cs[pos] = src[i];
    }
}

// ---------------- batched CSR gather (warp per node, fp16 rows) -------------
__global__ void gather_all_kernel(const __half* __restrict__ hin_base,
                                  const int* __restrict__ off_all,
                                  const int* __restrict__ csr_all,
                                  const float* __restrict__ dout_all,
                                  __half* __restrict__ agg) {
    int p = blockIdx.y;
    int c = p >> 1;
    const __half* h = hin_base + (size_t)c * NH_;
    const int* off = off_all + p * (NN_ + 1);
    const int* csr = csr_all + (size_t)p * EE_;
    const float* dout = dout_all + p * NN_;
    __half* out = agg + (size_t)p * NH_;

    int warp = (blockIdx.x * blockDim.x + threadIdx.x) >> 5;
    int lane = threadIdx.x & 31;
    if (warp >= NN_) return;
    int b = off[warp], e = off[warp + 1];
    const uint2* h4 = (const uint2*)h;
    float ax = 0.f, ay = 0.f, az = 0.f, aw = 0.f;
    int i = b;
    for (; i + 1 < e; i += 2) {
        int s0 = csr[i], s1 = csr[i + 1];
        float w0 = dout[s0], w1 = dout[s1];
        uint2 u0 = h4[(size_t)s0 * 32 + lane];
        uint2 u1 = h4[(size_t)s1 * 32 + lane];
        float2 a0 = __half22float2(*(__half2*)&u0.x);
        float2 b0 = __half22float2(*(__half2*)&u0.y);
        float2 a1 = __half22float2(*(__half2*)&u1.x);
        float2 b1 = __half22float2(*(__half2*)&u1.y);
        ax += w0 * a0.x + w1 * a1.x;
        ay += w0 * a0.y + w1 * a1.y;
        az += w0 * b0.x + w1 * b1.x;
        aw += w0 * b0.y + w1 * b1.y;
    }
    if (i < e) {
        int s0 = csr[i];
        float w0 = dout[s0];
        uint2 u0 = h4[(size_t)s0 * 32 + lane];
        float2 a0 = __half22float2(*(__half2*)&u0.x);
        float2 b0 = __half22float2(*(__half2*)&u0.y);
        ax += w0 * a0.x; ay += w0 * a0.y; az += w0 * b0.x; aw += w0 * b0.y;
    }
    uint2 st;
    *(__half2*)&st.x = __floats2half2_rn(ax, ay);
    *(__half2*)&st.y = __floats2half2_rn(az, aw);
    ((uint2*)out)[(size_t)warp * 32 + lane] = st;
}

// ---------------- fp16 MMA helpers ------------------------------------------
__device__ __forceinline__ void mma16(float* c, unsigned a0, unsigned a1, unsigned a2,
                                      unsigned a3, unsigned b0, unsigned b1) {
    asm volatile(
        "mma.sync.aligned.m16n8k16.row.col.f32.f16.f16.f32 "
        "{%0,%1,%2,%3},{%4,%5,%6,%7},{%8,%9},{%0,%1,%2,%3};"
        : "+f"(c[0]), "+f"(c[1]), "+f"(c[2]), "+f"(c[3])
        : "r"(a0), "r"(a1), "r"(a2), "r"(a3), "r"(b0), "r"(b1));
}

#define AK 40      // K-chunk row pad (32 + 8): row stride 20 banks -> conflict-free
#define HSP 136    // hs row pad: row stride 4 banks -> conflict-free

#define LOADU(ptr) (*(const unsigned*)(ptr))

// fp16 MMA over one BK=32 chunk; A rows [row][AK], B rows [n][AK]
// acc[2][NF][4]; per warp: rows mbase(+mf*16)+grp, cols nbase+nf*8+grp
#define MMA_CHUNK(As_, Bs_, acc_, NF_, nbase_)                                    \
    _Pragma("unroll")                                                             \
    for (int kk = 0; kk < 32; kk += 16) {                                         \
        unsigned a_[2][4];                                                        \
        _Pragma("unroll")                                                         \
        for (int mf = 0; mf < 2; mf++) {                                          \
            int r0_ = mbase + mf * 16 + grp;                                      \
            a_[mf][0] = LOADU(&As_[r0_][kk + 2 * tig]);                           \
            a_[mf][1] = LOADU(&As_[r0_ + 8][kk + 2 * tig]);                       \
            a_[mf][2] = LOADU(&As_[r0_][kk + 2 * tig + 8]);                       \
            a_[mf][3] = LOADU(&As_[r0_ + 8][kk + 2 * tig + 8]);                   \
        }                                                                         \
        _Pragma("unroll")                                                         \
        for (int nf = 0; nf < NF_; nf++) {                                        \
            int n_ = nbase_ + nf * 8 + grp;                                       \
            unsigned b0_ = LOADU(&Bs_[n_][kk + 2 * tig]);                         \
            unsigned b1_ = LOADU(&Bs_[n_][kk + 2 * tig + 8]);                     \
            mma16(acc_[0][nf], a_[0][0], a_[0][1], a_[0][2], a_[0][3], b0_, b1_); \
            mma16(acc_[1][nf], a_[1][0], a_[1][1], a_[1][2], a_[1][3], b0_, b1_); \
        }                                                                         \
    }

// ---------------- h0 GEMM: h0 = tanh(x @ Wf16^T) -> fp16, batched over 4 ----
__global__ __launch_bounds__(256)
void h0_gemm_kernel(const float* __restrict__ x_attr, const float* __restrict__ x_stru,
                    const __half* __restrict__ wf16, __half* __restrict__ h0b) {
    __shared__ __half As[128][AK];
    __shared__ __half Bs[128][AK];

    const int c = blockIdx.y;
    const int s = c >> 1;
    const float* A = (c & 1) ? x_stru : x_attr;
    const __half* B = wf16 + (size_t)s * HH_ * FF_;
    __half* C = h0b + (size_t)c * NH_;

    const int tid  = threadIdx.x;
    const int lane = tid & 31;
    const int warp = tid >> 5;
    const int grp  = lane >> 2;
    const int tig  = lane & 3;
    const int wm   = warp >> 1;
    const int wn   = warp & 1;
    const int mbase = wm * 32;
    const int nbase = wn * 64;
    const int block_m = blockIdx.x * 128;

    float acc[2][8][4];
#pragma unroll
    for (int mf = 0; mf < 2; mf++)
#pragma unroll
        for (int nf = 0; nf < 8; nf++)
#pragma unroll
            for (int q = 0; q < 4; q++) acc[mf][nf][q] = 0.f;

    const int row = tid & 127;
    const int hb = tid >> 7;

    for (int k0 = 0; k0 < FF_; k0 += 32) {
        {   // A tile: fp32 -> fp16, [row][k]
            int gm = block_m + row;
            bool ok = (gm < NN_);
            const float* ap = A + (size_t)gm * FF_ + k0 + hb * 16;
            __half2 h2v[8];
#pragma unroll
            for (int j = 0; j < 4; j++) {
                float4 v;
                if (ok) v = *(const float4*)(ap + j * 4);
                else { v.x = v.y = v.z = v.w = 0.f; }
                h2v[j * 2 + 0] = __floats2half2_rn(v.x, v.y);
                h2v[j * 2 + 1] = __floats2half2_rn(v.z, v.w);
            }
            *(uint4*)&As[row][hb * 16]     = *(uint4*)&h2v[0];
            *(uint4*)&As[row][hb * 16 + 8] = *(uint4*)&h2v[4];
        }
        {   // B tile: fp16 [n][k] straight copy
            const __half* bp = B + (size_t)row * FF_ + k0 + hb * 16;
            *(uint4*)&Bs[row][hb * 16]     = *(const uint4*)bp;
            *(uint4*)&Bs[row][hb * 16 + 8] = *(const uint4*)(bp + 8);
        }
        __syncthreads();
        MMA_CHUNK(As, Bs, acc, 8, nbase)
        __syncthreads();
    }
#pragma unroll
    for (int mf = 0; mf < 2; mf++) {
        int r0 = block_m + mbase + mf * 16 + grp;
#pragma unroll
        for (int nf = 0; nf < 8; nf++) {
            int col = nbase + nf * 8 + tig * 2;
#pragma unroll
            for (int half = 0; half < 2; half++) {
                int r = r0 + half * 8;
                if (r >= NN_) continue;
                *(__half2*)(C + (size_t)r * HH_ + col) =
                    __floats2half2_rn(tanhf(acc[mf][nf][half * 2 + 0]),
                                      tanhf(acc[mf][nf][half * 2 + 1]));
            }
        }
    }
}

// ---------------- batched fused conv GEMM + attention score (fp16 MMA) ------
// PHASE 0: blockIdx.y = q in 0..15: c=q>>2, li=(q>>1)&1 (li=0 -> l=1, li=1 -> l=0), r=q&1
// PHASE 1: blockIdx.y = q in 0..7:  c=q>>1, r=q&1, l=1
template <int PHASE>
__global__ __launch_bounds__(256)
void het_all_kernel(const __half* __restrict__ agg,
                    const __half* __restrict__ cw16, const float* __restrict__ convB,
                    const __half* __restrict__ w116, const float* __restrict__ attnB1,
                    const float* __restrict__ attnW2,
                    const float* __restrict__ din_all,
                    __half* __restrict__ hs_all, float* __restrict__ s_all) {
    extern __shared__ char smraw[];
    __half (*As)[AK]   = (__half(*)[AK])(smraw);                        // 10240 B
    __half (*Bs)[AK]   = (__half(*)[AK])(smraw + 128 * AK * 2);         // 10240 B
    __half (*HSs)[HSP] = (__half(*)[HSP])(smraw + 2 * 128 * AK * 2);    // 34816 B
    float* s_sm = (float*)(smraw + 2 * 128 * AK * 2 + 128 * HSP * 2);   // 512 B

    const int q = blockIdx.y;
    int c, l, r;
    if (PHASE == 0) { c = q >> 2; l = ((q >> 1) & 1) ? 0 : 1; r = q & 1; }
    else            { c = q >> 1; l = 1; r = q & 1; }
    const int s = c >> 1;
    const int p = c * 2 + r;
    const int m1 = (s * 2 + l) * 2 + r;   // conv matrix index
    const int m2 = s * 2 + l;             // attn matrix index

    const __half* A   = agg + (size_t)p * NH_;
    const __half* W   = cw16 + (size_t)m1 * HH_ * HH_;
    const float* bias = convB + (size_t)m1 * HH_;
    const __half* W1  = w116 + (size_t)m2 * QQ_ * HH_;
    const float* b1   = attnB1 + (size_t)m2 * QQ_;
    const float* w2   = attnW2 + (size_t)m2 * QQ_;
    const float* din  = din_all + p * NN_;
    __half* hs_out = hs_all + (size_t)q * NH_;
    float* s_out  = s_all + (size_t)q * NN_;

    const int tid  = threadIdx.x;
    const int lane = tid & 31;
    const int warp = tid >> 5;
    const int grp  = lane >> 2;
    const int tig  = lane & 3;
    const int wm   = warp >> 1;
    const int wn   = warp & 1;
    const int mbase = wm * 32;
    const int block_m = blockIdx.x * 128;
    const int row = tid & 127;
    const int hb = tid >> 7;

    if (tid < 128) s_sm[tid] = 0.f;

    // ---------------- stage 1: conv GEMM (K=128, N=128) ----------------
    float acc[2][8][4];
#pragma unroll
    for (int mf = 0; mf < 2; mf++)
#pragma unroll
        for (int nf = 0; nf < 8; nf++)
#pragma unroll
            for (int qq = 0; qq < 4; qq++) acc[mf][nf][qq] = 0.f;

    for (int k0 = 0; k0 < HH_; k0 += 32) {
        {   // A tile: fp16 [row][k]
            int gm = block_m + row;
            if (gm < NN_) {
                const __half* ap = A + (size_t)gm * HH_ + k0 + hb * 16;
                *(uint4*)&As[row][hb * 16]     = *(const uint4*)ap;
                *(uint4*)&As[row][hb * 16 + 8] = *(const uint4*)(ap + 8);
            } else {
                *(uint4*)&As[row][hb * 16]     = make_uint4(0, 0, 0, 0);
                *(uint4*)&As[row][hb * 16 + 8] = make_uint4(0, 0, 0, 0);
            }
        }
        {   // B tile: conv weight fp16 [n][k]
            const __half* bp = W + (size_t)row * HH_ + k0 + hb * 16;
            *(uint4*)&Bs[row][hb * 16]     = *(const uint4*)bp;
            *(uint4*)&Bs[row][hb * 16 + 8] = *(const uint4*)(bp + 8);
        }
        __syncthreads();
        MMA_CHUNK(As, Bs, acc, 8, (wn * 64))
        __syncthreads();
    }

    // stage-1 epilogue: hs = acc*din + b; fp16 global write + [row][col] smem
#pragma unroll
    for (int mf = 0; mf < 2; mf++) {
        int rl0 = mbase + mf * 16 + grp;
#pragma unroll
        for (int nf = 0; nf < 8; nf++) {
            int col = wn * 64 + nf * 8 + tig * 2;
            float bc0 = bias[col], bc1 = bias[col + 1];
#pragma unroll
            for (int half = 0; half < 2; half++) {
                int rl = rl0 + half * 8;
                int rg = block_m + rl;
                float rs = (rg < NN_) ? din[rg] : 0.f;
                float v0 = acc[mf][nf][half * 2 + 0] * rs + bc0;
                float v1 = acc[mf][nf][half * 2 + 1] * rs + bc1;
                __half2 hv = __floats2half2_rn(v0, v1);
                *(__half2*)&HSs[rl][col] = hv;
                if (rg < NN_)
                    *(__half2*)(hs_out + (size_t)rg * HH_ + col) = hv;
            }
        }
    }
    __syncthreads();

    // ---------------- stage 2: t = tanh(hs@W1 + b1); s = t.w2 ----------------
    float acc2[2][4][4];
#pragma unroll
    for (int mf = 0; mf < 2; mf++)
#pragma unroll
        for (int nf = 0; nf < 4; nf++)
#pragma unroll
            for (int qq = 0; qq < 4; qq++) acc2[mf][nf][qq] = 0.f;

    for (int k0 = 0; k0 < HH_; k0 += 32) {
        {   // W1 chunk fp16 [n=64][k]: 64 rows x 32 halves
            int n = tid & 63;
            int kb = tid >> 6;          // 0..3 -> 8 halves each
            const __half* bp = W1 + (size_t)n * HH_ + k0 + kb * 8;
            *(uint4*)&Bs[n][kb * 8] = *(const uint4*)bp;
        }
        __syncthreads();
#pragma unroll
        for (int kk = 0; kk < 32; kk += 16) {
            unsigned a[2][4];
#pragma unroll
            for (int mf = 0; mf < 2; mf++) {
                int r0 = mbase + mf * 16 + grp;
                a[mf][0] = LOADU(&HSs[r0][k0 + kk + 2 * tig]);
                a[mf][1] = LOADU(&HSs[r0 + 8][k0 + kk + 2 * tig]);
                a[mf][2] = LOADU(&HSs[r0][k0 + kk + 2 * tig + 8]);
                a[mf][3] = LOADU(&HSs[r0 + 8][k0 + kk + 2 * tig + 8]);
            }
#pragma unroll
            for (int nf = 0; nf < 4; nf++) {
                int n = wn * 32 + nf * 8 + grp;
                unsigned b0 = LOADU(&Bs[n][kk + 2 * tig]);
                unsigned b1 = LOADU(&Bs[n][kk + 2 * tig + 8]);
                mma16(acc2[0][nf], a[0][0], a[0][1], a[0][2], a[0][3], b0, b1);
                mma16(acc2[1][nf], a[1][0], a[1][1], a[1][2], a[1][3], b0, b1);
            }
        }
        __syncthreads();
    }

    float part[2][2] = {{0.f, 0.f}, {0.f, 0.f}};
#pragma unroll
    for (int mf = 0; mf < 2; mf++)
#pragma unroll
        for (int nf = 0; nf < 4; nf++) {
            int col = wn * 32 + nf * 8 + tig * 2;
            float bc0 = b1[col], bc1 = b1[col + 1];
            float w20 = w2[col], w21 = w2[col + 1];
#pragma unroll
            for (int half = 0; half < 2; half++) {
                float v0 = tanhf(acc2[mf][nf][half * 2 + 0] + bc0);
                float v1 = tanhf(acc2[mf][nf][half * 2 + 1] + bc1);
                part[mf][half] += v0 * w20 + v1 * w21;
            }
        }
#pragma unroll
    for (int o = 1; o <= 2; o <<= 1) {
#pragma unroll
        for (int mf = 0; mf < 2; mf++)
#pragma unroll
            for (int half = 0; half < 2; half++)
                part[mf][half] += __shfl_xor_sync(0xffffffffu, part[mf][half], o);
    }
    if (tig == 0) {
#pragma unroll
        for (int mf = 0; mf < 2; mf++)
#pragma unroll
            for (int half = 0; half < 2; half++)
                atomicAdd(&s_sm[mbase + mf * 16 + grp + half * 8], part[mf][half]);
    }
    __syncthreads();
    if (tid < 128) {
        int rg = block_m + tid;
        if (rg < NN_) s_out[rg] = s_sm[tid];
    }
}

// ---------------- batched attention combine (fp16 hs/out) -------------------
template <int PHASE>
__global__ void combine_all_kernel(const __half* __restrict__ hs_all,
                                   const float* __restrict__ s_all,
                                   __half* __restrict__ h1b, __half* __restrict__ hAb,
                                   __half* __restrict__ h2b) {
    const int u = blockIdx.y;
    int q0, c;
    __half* outb;
    if (PHASE == 0) {
        c = u >> 1;
        int li = u & 1;
        q0 = c * 4 + li * 2;
        outb = (li == 0 ? h1b : hAb);
    } else {
        c = u;
        q0 = c * 2;
        outb = h2b;
    }
    const __half* hs0 = hs_all + (size_t)q0 * NH_;
    const __half* hs1 = hs_all + (size_t)(q0 + 1) * NH_;
    const float* s0 = s_all + (size_t)q0 * NN_;
    const float* s1 = s_all + (size_t)(q0 + 1) * NN_;
    __half* out = outb + (size_t)c * NH_;

    int warp = (blockIdx.x * blockDim.x + threadIdx.x) >> 5;
    int lane = threadIdx.x & 31;
    if (warp >= NN_) return;
    float sv0 = s0[warp], sv1 = s1[warp];
    float m = fmaxf(sv0, sv1);
    float e0 = expf(sv0 - m), e1 = expf(sv1 - m);
    float a0 = e0 / (e0 + e1), a1 = 1.f - a0;
    uint2 u0 = ((const uint2*)(hs0 + (size_t)warp * HH_))[lane];
    uint2 u1 = ((const uint2*)(hs1 + (size_t)warp * HH_))[lane];
    float2 f0a = __half22float2(*(__half2*)&u0.x);
    float2 f0b = __half22float2(*(__half2*)&u0.y);
    float2 f1a = __half22float2(*(__half2*)&u1.x);
    float2 f1b = __half22float2(*(__half2*)&u1.y);
    uint2 st;
    *(__half2*)&st.x = __floats2half2_rn(a0 * f0a.x + a1 * f1a.x, a0 * f0a.y + a1 * f1a.y);
    *(__half2*)&st.y = __floats2half2_rn(a0 * f0b.x + a1 * f1b.x, a0 * f0b.y + a1 * f1b.y);
    ((uint2*)(out + (size_t)warp * HH_))[lane] = st;
}

// ---------------- final GEMM: y = [h0|h1|h2](fp16) @ Wc16^T -> fp32 out -----
__global__ __launch_bounds__(256)
void final_gemm_kernel(const __half* __restrict__ h0b, const __half* __restrict__ h1b,
                       const __half* __restrict__ h2b, const __half* __restrict__ wc16,
                       float* __restrict__ Cout) {
    __shared__ __half As[128][AK];
    __shared__ __half Bs[128][AK];

    const int c = blockIdx.y;
    const int s = c >> 1;
    const __half* B = wc16 + (size_t)s * HH_ * (3 * HH_);
    float* C = Cout + (size_t)c * NH_;

    const int tid  = threadIdx.x;
    const int lane = tid & 31;
    const int warp = tid >> 5;
    const int grp  = lane >> 2;
    const int tig  = lane & 3;
    const int wm   = warp >> 1;
    const int wn   = warp & 1;
    const int mbase = wm * 32;
    const int nbase = wn * 64;
    const int block_m = blockIdx.x * 128;
    const int row = tid & 127;
    const int hb = tid >> 7;

    float acc[2][8][4];
#pragma unroll
    for (int mf = 0; mf < 2; mf++)
#pragma unroll
        for (int nf = 0; nf < 8; nf++)
#pragma unroll
            for (int q = 0; q < 4; q++) acc[mf][nf][q] = 0.f;

    for (int k0 = 0; k0 < 3 * HH_; k0 += 32) {
        int seg = k0 >> 7;
        int kseg = k0 & 127;
        const __half* A = ((seg == 0) ? h0b : ((seg == 1) ? h1b : h2b)) + (size_t)c * NH_;
        {
            int gm = block_m + row;
            if (gm < NN_) {
                const __half* ap = A + (size_t)gm * HH_ + kseg + hb * 16;
                *(uint4*)&As[row][hb * 16]     = *(const uint4*)ap;
                *(uint4*)&As[row][hb * 16 + 8] = *(const uint4*)(ap + 8);
            } else {
                *(uint4*)&As[row][hb * 16]     = make_uint4(0, 0, 0, 0);
                *(uint4*)&As[row][hb * 16 + 8] = make_uint4(0, 0, 0, 0);
            }
        }
        {
            const __half* bp = B + (size_t)row * (3 * HH_) + k0 + hb * 16;
            *(uint4*)&Bs[row][hb * 16]     = *(const uint4*)bp;
            *(uint4*)&Bs[row][hb * 16 + 8] = *(const uint4*)(bp + 8);
        }
        __syncthreads();
        MMA_CHUNK(As, Bs, acc, 8, nbase)
        __syncthreads();
    }
#pragma unroll
    for (int mf = 0; mf < 2; mf++) {
        int r0 = block_m + mbase + mf * 16 + grp;
#pragma unroll
        for (int nf = 0; nf < 8; nf++) {
            int col = nbase + nf * 8 + tig * 2;
#pragma unroll
            for (int half = 0; half < 2; half++) {
                int r = r0 + half * 8;
                if (r >= NN_) continue;
                float2 st;
                st.x = acc[mf][nf][half * 2 + 0];
                st.y = acc[mf][nf][half * 2 + 1];
                *(float2*)(C + (size_t)r * HH_ + col) = st;
            }
        }
    }
}

// ---------------- host orchestration ----------------------------------------
extern "C" void kernel_launch(void* const* d_in, const int* in_sizes, int n_in,
                              void* d_out, int out_size) {
    const float* x_attr  = (const float*)d_in[0];
    const float* x_stru  = (const float*)d_in[1];
    const int*   e_attr  = (const int*)  d_in[2];
    const int*   e_stru  = (const int*)  d_in[3];
    const float* Wf      = (const float*)d_in[4];   // (2,H,F)
    const float* convW   = (const float*)d_in[5];   // (2,2,2,H,H)
    const float* convB   = (const float*)d_in[6];   // (2,2,2,H)
    const float* attnW1  = (const float*)d_in[7];   // (2,2,H,Q)
    const float* attnB1  = (const float*)d_in[8];   // (2,2,Q)
    const float* attnW2  = (const float*)d_in[9];   // (2,2,Q)
    const float* Wc      = (const float*)d_in[10];  // (2,H,3H)
    float* out = (float*)d_out;

    __half *h0, *h1, *hA, *h2, *agg, *hs, *wf16, *cw16, *w116, *wc16;
    float *sb, *din, *dout;
    int *cnt_in, *cnt_out, *cursor, *off, *csr;
    cudaGetSymbolAddress((void**)&h0,  g_h0);
    cudaGetSymbolAddress((void**)&h1,  g_h1);
    cudaGetSymbolAddress((void**)&hA,  g_hA);
    cudaGetSymbolAddress((void**)&h2,  g_h2);
    cudaGetSymbolAddress((void**)&agg, g_agg);
    cudaGetSymbolAddress((void**)&hs,  g_hs);
    cudaGetSymbolAddress((void**)&sb,  g_s);
    cudaGetSymbolAddress((void**)&wf16, g_wf16);
    cudaGetSymbolAddress((void**)&cw16, g_cw16);
    cudaGetSymbolAddress((void**)&w116, g_w116);
    cudaGetSymbolAddress((void**)&wc16, g_wc16);
    cudaGetSymbolAddress((void**)&din,  g_din);
    cudaGetSymbolAddress((void**)&dout, g_dout);
    cudaGetSymbolAddress((void**)&cnt_in,  g_cnt_in);
    cudaGetSymbolAddress((void**)&cnt_out, g_cnt_out);
    cudaGetSymbolAddress((void**)&cursor,  g_cursor);
    cudaGetSymbolAddress((void**)&off, g_off);
    cudaGetSymbolAddress((void**)&csr, g_csr);

    const int TB = 256;
    const int gridM = (NN_ + 127) / 128;
    const int gridWarp = (NN_ + 7) / 8;
    const int HET_SMEM = 2 * 128 * AK * 2 + 128 * HSP * 2 + 512;   // ~56 KB
    cudaFuncSetAttribute(het_all_kernel<0>, cudaFuncAttributeMaxDynamicSharedMemorySize, HET_SMEM);
    cudaFuncSetAttribute(het_all_kernel<1>, cudaFuncAttributeMaxDynamicSharedMemorySize, HET_SMEM);

    // 0) weight prep (fp32 -> fp16, [n][k] layouts)
    prep_weights_kernel<<<256, TB>>>(Wf, convW, attnW1, Wc, wf16, cw16, w116, wc16);

    // 1) zero histogram counters
    zero_int_kernel<<<512, TB>>>(cnt_in, 8 * NN_);
    zero_int_kernel<<<512, TB>>>(cnt_out, 8 * NN_);

    // 2) h0 for all 4 runs (fp16 out)
    h0_gemm_kernel<<<dim3(gridM, 4), TB>>>(x_attr, x_stru, wf16, h0);

    // 3) CSR build, all 8 pairs batched
    hist_all_kernel<<<dim3(256, 8), TB>>>(e_attr, e_stru, cnt_out, cnt_in);
    deg_all_kernel<<<(8 * NN_ + 255) / 256, TB>>>(cnt_in, cnt_out, din, dout);
    scan_all_kernel<<<8, 1024>>>(cnt_in, off, cursor);
    scatter_all_kernel<<<dim3(256, 8), TB>>>(e_attr, e_stru, cursor, csr);

    // 4) phase A: gather over h0 (8 pairs), het (16 combos), combine (8)
    gather_all_kernel<<<dim3(gridWarp, 8), TB>>>(h0, off, csr, dout, agg);
    het_all_kernel<0><<<dim3(gridM, 16), TB, HET_SMEM>>>(
        agg, cw16, convB, w116, attnB1, attnW2, din, hs, sb);
    combine_all_kernel<0><<<dim3(gridWarp, 8), TB>>>(hs, sb, h1, hA, h2);

    // 5) phase B: gather over hA (8), het (8), combine (4)
    gather_all_kernel<<<dim3(gridWarp, 8), TB>>>(hA, off, csr, dout, agg);
    het_all_kernel<1><<<dim3(gridM, 8), TB, HET_SMEM>>>(
        agg, cw16, convB, w116, attnB1, attnW2, din, hs, sb);
    combine_all_kernel<1><<<dim3(gridWarp, 4), TB>>>(hs, sb, h1, hA, h2);

    // 6) final: y = [h0|h1|h2] @ Wc^T for all 4 runs (fp32 out)
    final_gemm_kernel<<<dim3(gridM, 4), TB>>>(h0, h1, h2, wc16, out);
}

// round 10
// speedup vs baseline: 1.7106x; 1.1097x over previous
#include <cuda_runtime.h>
#include <cuda_fp16.h>
#include <math.h>

// Problem constants
#define NN_ 50000
#define EE_ 600000
#define HH_ 128
#define FF_ 256
#define QQ_ 64
#define NH_ (NN_ * HH_)

// ---------------- scratch (device globals; no dynamic allocation) ----------
__device__ __half g_h0 [4 * NH_];
__device__ __half g_h1 [4 * NH_];
__device__ __half g_hA [4 * NH_];
__device__ __half g_h2 [4 * NH_];
__device__ __half g_agg[8 * NH_];
__device__ __half g_hs [16 * NH_];
__device__ float  g_s  [16 * NN_];
__device__ __half g_x16[2 * NN_ * FF_];          // fp16 copies of x_attr/x_stru

// fp16 weight copies, [n][k] layout (transposed where needed by prep kernel)
__device__ __half g_wf16 [2 * HH_ * FF_];        // [s][n=128][k=256]
__device__ __half g_cw16 [8 * HH_ * HH_];        // [m][n=128][k=128]
__device__ __half g_w116 [4 * QQ_ * HH_];        // [m][n=64][k=128]
__device__ __half g_wc16 [2 * HH_ * 3 * HH_];    // [s][n=128][k=384]

__device__ int   g_cnt_in [8 * NN_];
__device__ int   g_cnt_out[8 * NN_];
__device__ int   g_cursor [8 * NN_];
__device__ int   g_off    [8 * (NN_ + 1)];
__device__ int   g_csr    [8 * EE_];
__device__ float g_din    [8 * NN_];
__device__ float g_dout   [8 * NN_];

// ---------------- helpers ---------------------------------------------------
__device__ __forceinline__ const int* edge_ptr_dev(const int* e_attr, const int* e_stru,
                                                   int p, int which) {
    int c = p >> 1, r = p & 1;
    int sign = c >> 1;
    const int* E = (c & 1) ? e_stru : e_attr;
    return E + ((size_t)((sign * 2 + r) * 2 + which)) * EE_;
}

// ---------------- prep kernels ----------------------------------------------
__global__ void prep_weights_kernel(const float* __restrict__ Wf, const float* __restrict__ convW,
                                    const float* __restrict__ attnW1, const float* __restrict__ Wc,
                                    __half* __restrict__ wf16, __half* __restrict__ cw16,
                                    __half* __restrict__ w116, __half* __restrict__ wc16) {
    const int NWF = 2 * HH_ * FF_;
    const int NCW = 8 * HH_ * HH_;
    const int NW1 = 4 * QQ_ * HH_;
    const int NWC = 2 * HH_ * 3 * HH_;
    for (int i = blockIdx.x * blockDim.x + threadIdx.x;
         i < NWF + NCW + NW1 + NWC; i += gridDim.x * blockDim.x) {
        if (i < NWF) {
            wf16[i] = __float2half_rn(Wf[i]);
        } else if (i < NWF + NCW) {
            int j = i - NWF;
            int m = j / (HH_ * HH_), t = j % (HH_ * HH_);
            int n = t / HH_, k = t % HH_;
            cw16[j] = __float2half_rn(convW[m * HH_ * HH_ + k * HH_ + n]);
        } else if (i < NWF + NCW + NW1) {
            int j = i - NWF - NCW;
            int m = j / (QQ_ * HH_), t = j % (QQ_ * HH_);
            int n = t / HH_, k = t % HH_;
            w116[j] = __float2half_rn(attnW1[m * HH_ * QQ_ + k * QQ_ + n]);
        } else {
            int j = i - NWF - NCW - NW1;
            wc16[j] = __float2half_rn(Wc[j]);
        }
    }
}

__global__ void convert_x_kernel(const float* __restrict__ xa, const float* __restrict__ xs,
                                 __half* __restrict__ x16) {
    const int Q4 = NN_ * FF_ / 4;
    for (int i = blockIdx.x * blockDim.x + threadIdx.x; i < Q4; i += gridDim.x * blockDim.x) {
        float4 va = ((const float4*)xa)[i];
        float4 vs = ((const float4*)xs)[i];
        __half2 ha0 = __floats2half2_rn(va.x, va.y), ha1 = __floats2half2_rn(va.z, va.w);
        __half2 hs0 = __floats2half2_rn(vs.x, vs.y), hs1 = __floats2half2_rn(vs.z, vs.w);
        ((uint2*)x16)[i] = make_uint2(*(unsigned*)&ha0, *(unsigned*)&ha1);
        ((uint2*)(x16 + (size_t)NN_ * FF_))[i] = make_uint2(*(unsigned*)&hs0, *(unsigned*)&hs1);
    }
}

// ---------------- CSR-build kernels (batched over 8 pairs) ------------------
__global__ void zero_int_kernel(int* p, int n) {
    for (int i = blockIdx.x * blockDim.x + threadIdx.x; i < n; i += gridDim.x * blockDim.x)
        p[i] = 0;
}

__global__ void hist_all_kernel(const int* __restrict__ e_attr, const int* __restrict__ e_stru,
                                int* __restrict__ cnt_out, int* __restrict__ cnt_in) {
    int p = blockIdx.y;
    const int* src = edge_ptr_dev(e_attr, e_stru, p, 0);
    const int* dst = edge_ptr_dev(e_attr, e_stru, p, 1);
    int* co = cnt_out + p * NN_;
    int* ci = cnt_in  + p * NN_;
    for (int i = blockIdx.x * blockDim.x + threadIdx.x; i < EE_; i += gridDim.x * blockDim.x) {
        atomicAdd(&co[src[i]], 1);
        atomicAdd(&ci[dst[i]], 1);
    }
}

__global__ void deg_all_kernel(const int* __restrict__ cin, const int* __restrict__ cout,
                               float* __restrict__ din, float* __restrict__ dout) {
    for (int i = blockIdx.x * blockDim.x + threadIdx.x; i < 8 * NN_; i += gridDim.x * blockDim.x) {
        int a = cin[i];  if (a < 1) a = 1;
        int b = cout[i]; if (b < 1) b = 1;
        din [i] = rsqrtf((float)a);
        dout[i] = rsqrtf((float)b);
    }
}

__global__ void scan_all_kernel(const int* __restrict__ cnt_all, int* __restrict__ off_all,
                                int* __restrict__ cur_all) {
    __shared__ int sh[1024];
    const int p = blockIdx.x;
    const int* cnt = cnt_all + p * NN_;
    int* off = off_all + p * (NN_ + 1);
    int* cur = cur_all + p * NN_;
    const int t  = threadIdx.x;
    const int CH = (NN_ + 1023) / 1024;
    const int base = t * CH;
    int s = 0;
    for (int i = 0; i < CH; i++) { int idx = base + i; if (idx < NN_) s += cnt[idx]; }
    sh[t] = s;
    __syncthreads();
    for (int d = 1; d < 1024; d <<= 1) {
        int v = (t >= d) ? sh[t - d] : 0;
        __syncthreads();
        sh[t] += v;
        __syncthreads();
    }
    int run = (t == 0) ? 0 : sh[t - 1];
    for (int i = 0; i < CH; i++) {
        int idx = base + i;
        if (idx < NN_) { off[idx] = run; cur[idx] = run; run += cnt[idx]; }
    }
    if (t == 0) off[NN_] = sh[1023];
}

__global__ void scatter_all_kernel(const int* __restrict__ e_attr, const int* __restrict__ e_stru,
                                   int* __restrict__ cursor, int* __restrict__ csr) {
    int p = blockIdx.y;
    const int* src = edge_ptr_dev(e_attr, e_stru, p, 0);
    const int* dst = edge_ptr_dev(e_attr, e_stru, p, 1);
    int* cu = cursor + p * NN_;
    int* cs = csr + (size_t)p * EE_;
    for (int i = blockIdx.x * blockDim.x + threadIdx.x; i < EE_; i += gridDim.x * blockDim.x) {
        int pos = atomicAdd(&cu[dst[i]], 1);
        cs[pos] = src[i];
    }
}

// ---------------- batched CSR gather (warp per node, fp16 rows) -------------
__global__ void gather_all_kernel(const __half* __restrict__ hin_base,
                                  const int* __restrict__ off_all,
                                  const int* __restrict__ csr_all,
                                  const float* __restrict__ dout_all,
                                  __half* __restrict__ agg) {
    int p = blockIdx.y;
    int c = p >> 1;
    const __half* h = hin_base + (size_t)c * NH_;
    const int* off = off_all + p * (NN_ + 1);
    const int* csr = csr_all + (size_t)p * EE_;
    const float* dout = dout_all + p * NN_;
    __half* out = agg + (size_t)p * NH_;

    int warp = (blockIdx.x * blockDim.x + threadIdx.x) >> 5;
    int lane = threadIdx.x & 31;
    if (warp >= NN_) return;
    int b = off[warp], e = off[warp + 1];
    const uint2* h4 = (const uint2*)h;
    float ax = 0.f, ay = 0.f, az = 0.f, aw = 0.f;
    int i = b;
    for (; i + 1 < e; i += 2) {
        int s0 = csr[i], s1 = csr[i + 1];
        float w0 = dout[s0], w1 = dout[s1];
        uint2 u0 = h4[(size_t)s0 * 32 + lane];
        uint2 u1 = h4[(size_t)s1 * 32 + lane];
        float2 a0 = __half22float2(*(__half2*)&u0.x);
        float2 b0 = __half22float2(*(__half2*)&u0.y);
        float2 a1 = __half22float2(*(__half2*)&u1.x);
        float2 b1 = __half22float2(*(__half2*)&u1.y);
        ax += w0 * a0.x + w1 * a1.x;
        ay += w0 * a0.y + w1 * a1.y;
        az += w0 * b0.x + w1 * b1.x;
        aw += w0 * b0.y + w1 * b1.y;
    }
    if (i < e) {
        int s0 = csr[i];
        float w0 = dout[s0];
        uint2 u0 = h4[(size_t)s0 * 32 + lane];
        float2 a0 = __half22float2(*(__half2*)&u0.x);
        float2 b0 = __half22float2(*(__half2*)&u0.y);
        ax += w0 * a0.x; ay += w0 * a0.y; az += w0 * b0.x; aw += w0 * b0.y;
    }
    uint2 st;
    *(__half2*)&st.x = __floats2half2_rn(ax, ay);
    *(__half2*)&st.y = __floats2half2_rn(az, aw);
    ((uint2*)out)[(size_t)warp * 32 + lane] = st;
}

// ---------------- fp16 MMA / async-copy / ldmatrix helpers ------------------
__device__ __forceinline__ void mma16(float* c, unsigned a0, unsigned a1, unsigned a2,
                                      unsigned a3, unsigned b0, unsigned b1) {
    asm volatile(
        "mma.sync.aligned.m16n8k16.row.col.f32.f16.f16.f32 "
        "{%0,%1,%2,%3},{%4,%5,%6,%7},{%8,%9},{%0,%1,%2,%3};"
        : "+f"(c[0]), "+f"(c[1]), "+f"(c[2]), "+f"(c[3])
        : "r"(a0), "r"(a1), "r"(a2), "r"(a3), "r"(b0), "r"(b1));
}

__device__ __forceinline__ unsigned smem_u32(const void* p) {
    return (unsigned)__cvta_generic_to_shared(p);
}
__device__ __forceinline__ void cp16(unsigned s, const void* g) {
    asm volatile("cp.async.ca.shared.global [%0], [%1], 16;" :: "r"(s), "l"(g));
}
__device__ __forceinline__ void cp_commit() { asm volatile("cp.async.commit_group;"); }
template <int N>
__device__ __forceinline__ void cp_wait() { asm volatile("cp.async.wait_group %0;" :: "n"(N)); }

__device__ __forceinline__ void ldsm4(unsigned& r0, unsigned& r1, unsigned& r2, unsigned& r3,
                                      unsigned a) {
    asm volatile("ldmatrix.sync.aligned.m8n8.x4.shared.b16 {%0,%1,%2,%3}, [%4];"
                 : "=r"(r0), "=r"(r1), "=r"(r2), "=r"(r3) : "r"(a));
}

#define AK 40      // K-chunk row pad: 80 B row stride (20 banks, 16B-aligned) -> ldmatrix conflict-free
#define HSP 136    // hs row pad: 272 B row stride (4-bank step) -> conflict-free

// ldmatrix.x4 address for the 16x16 tile at rows r0.., cols kk.. of T[.][S]
template <int S>
__device__ __forceinline__ unsigned frag_addr(const __half (*T)[S], int r0, int kk, int lane) {
    int lr = lane & 7;
    int sel = lane >> 3;
    int row = r0 + ((sel & 1) << 3) + lr;
    int col = kk + ((sel & 2) << 2);
    return smem_u32(&T[row][col]);
}

// one BK=32 chunk of MMA: A rows at mbase/mbase+16, B rows at nbase..nbase+NF*8
template <int SA, int SB, int NF>
__device__ __forceinline__ void mma_tile(const __half (*Am)[SA], int akoff, int mbase,
                                         const __half (*Bm)[SB], int nbase,
                                         float (&acc)[2][NF][4], int lane) {
#pragma unroll
    for (int kk = 0; kk < 32; kk += 16) {
        unsigned a[2][4];
#pragma unroll
        for (int mf = 0; mf < 2; mf++)
            ldsm4(a[mf][0], a[mf][1], a[mf][2], a[mf][3],
                  frag_addr<SA>(Am, mbase + mf * 16, akoff + kk, lane));
        unsigned b0[NF], b1[NF];
#pragma unroll
        for (int pr = 0; pr < NF / 2; pr++)
            ldsm4(b0[2 * pr], b0[2 * pr + 1], b1[2 * pr], b1[2 * pr + 1],
                  frag_addr<SB>(Bm, nbase + pr * 16, kk, lane));
#pragma unroll
        for (int nf = 0; nf < NF; nf++) {
            mma16(acc[0][nf], a[0][0], a[0][1], a[0][2], a[0][3], b0[nf], b1[nf]);
            mma16(acc[1][nf], a[1][0], a[1][1], a[1][2], a[1][3], b0[nf], b1[nf]);
        }
    }
}

// async tile copy: 128 rows x 32 halves from fp16 global [row][ld] at col k0
__device__ __forceinline__ void copy_tile_A(__half (*dst)[AK], const __half* A, int ld,
                                            int block_m, int k0, int tid, int M) {
    int row = tid & 127;
    int hb = tid >> 7;
    int gm = block_m + row;
    unsigned sa = smem_u32(&dst[row][hb * 16]);
    if (gm < M) {
        const __half* gp = A + (size_t)gm * ld + k0 + hb * 16;
        cp16(sa, gp);
        cp16(sa + 16, gp + 8);
    } else {
        *(uint4*)&dst[row][hb * 16]     = make_uint4(0, 0, 0, 0);
        *(uint4*)&dst[row][hb * 16 + 8] = make_uint4(0, 0, 0, 0);
    }
}
__device__ __forceinline__ void copy_tile_B(__half (*dst)[AK], const __half* B, int ld,
                                            int k0, int tid) {
    int row = tid & 127;
    int hb = tid >> 7;
    unsigned sb = smem_u32(&dst[row][hb * 16]);
    const __half* gp = B + (size_t)row * ld + k0 + hb * 16;
    cp16(sb, gp);
    cp16(sb + 16, gp + 8);
}

// ---------------- h0 GEMM: h0 = tanh(x16 @ Wf16^T) -> fp16, batched over 4 --
__global__ __launch_bounds__(256)
void h0_gemm_kernel(const __half* __restrict__ x16, const __half* __restrict__ wf16,
                    __half* __restrict__ h0b) {
    __shared__ __half As[2][128][AK];
    __shared__ __half Bs[2][128][AK];

    const int c = blockIdx.y;
    const int s = c >> 1;
    const __half* A = x16 + (size_t)(c & 1) * NN_ * FF_;
    const __half* B = wf16 + (size_t)s * HH_ * FF_;
    __half* C = h0b + (size_t)c * NH_;

    const int tid  = threadIdx.x;
    const int lane = tid & 31;
    const int warp = tid >> 5;
    const int grp  = lane >> 2;
    const int tig  = lane & 3;
    const int mbase = (warp >> 1) * 32;
    const int nbase = (warp & 1) * 64;
    const int block_m = blockIdx.x * 128;

    float acc[2][8][4];
#pragma unroll
    for (int mf = 0; mf < 2; mf++)
#pragma unroll
        for (int nf = 0; nf < 8; nf++)
#pragma unroll
            for (int q = 0; q < 4; q++) acc[mf][nf][q] = 0.f;

    const int NC = FF_ / 32;
    copy_tile_A(As[0], A, FF_, block_m, 0, tid, NN_);
    copy_tile_B(Bs[0], B, FF_, 0, tid);
    cp_commit();
    for (int k = 0; k < NC; k++) {
        if (k + 1 < NC) {
            copy_tile_A(As[(k + 1) & 1], A, FF_, block_m, (k + 1) * 32, tid, NN_);
            copy_tile_B(Bs[(k + 1) & 1], B, FF_, (k + 1) * 32, tid);
            cp_commit();
            cp_wait<1>();
        } else {
            cp_wait<0>();
        }
        __syncthreads();
        mma_tile<AK, AK, 8>(As[k & 1], 0, mbase, Bs[k & 1], nbase, acc, lane);
        __syncthreads();
    }
#pragma unroll
    for (int mf = 0; mf < 2; mf++) {
        int r0 = block_m + mbase + mf * 16 + grp;
#pragma unroll
        for (int nf = 0; nf < 8; nf++) {
            int col = nbase + nf * 8 + tig * 2;
#pragma unroll
            for (int half = 0; half < 2; half++) {
                int r = r0 + half * 8;
                if (r >= NN_) continue;
                *(__half2*)(C + (size_t)r * HH_ + col) =
                    __floats2half2_rn(tanhf(acc[mf][nf][half * 2 + 0]),
                                      tanhf(acc[mf][nf][half * 2 + 1]));
            }
        }
    }
}

// ---------------- batched fused conv GEMM + attention score -----------------
// PHASE 0: blockIdx.y = q in 0..15: c=q>>2, li=(q>>1)&1 (li=0 -> l=1, li=1 -> l=0), r=q&1
// PHASE 1: blockIdx.y = q in 0..7:  c=q>>1, r=q&1, l=1
template <int PHASE>
__global__ __launch_bounds__(256)
void het_all_kernel(const __half* __restrict__ agg,
                    const __half* __restrict__ cw16, const float* __restrict__ convB,
                    const __half* __restrict__ w116, const float* __restrict__ attnB1,
                    const float* __restrict__ attnW2,
                    const float* __restrict__ din_all,
                    __half* __restrict__ hs_all, float* __restrict__ s_all) {
    extern __shared__ char smraw[];
    __half (*As)[128][AK] = (__half(*)[128][AK])(smraw);
    __half (*Bs)[128][AK] = (__half(*)[128][AK])(smraw + 2 * 128 * AK * 2);
    __half (*HSs)[HSP]    = (__half(*)[HSP])   (smraw + 4 * 128 * AK * 2);
    float* s_sm = (float*)(smraw + 4 * 128 * AK * 2 + 128 * HSP * 2);

    const int q = blockIdx.y;
    int c, l, r;
    if (PHASE == 0) { c = q >> 2; l = ((q >> 1) & 1) ? 0 : 1; r = q & 1; }
    else            { c = q >> 1; l = 1; r = q & 1; }
    const int s = c >> 1;
    const int p = c * 2 + r;
    const int m1 = (s * 2 + l) * 2 + r;
    const int m2 = s * 2 + l;

    const __half* A   = agg + (size_t)p * NH_;
    const __half* W   = cw16 + (size_t)m1 * HH_ * HH_;
    const float* bias = convB + (size_t)m1 * HH_;
    const __half* W1  = w116 + (size_t)m2 * QQ_ * HH_;
    const float* b1   = attnB1 + (size_t)m2 * QQ_;
    const float* w2   = attnW2 + (size_t)m2 * QQ_;
    const float* din  = din_all + p * NN_;
    __half* hs_out = hs_all + (size_t)q * NH_;
    float* s_out  = s_all + (size_t)q * NN_;

    const int tid  = threadIdx.x;
    const int lane = tid & 31;
    const int warp = tid >> 5;
    const int grp  = lane >> 2;
    const int tig  = lane & 3;
    const int wn   = warp & 1;
    const int mbase = (warp >> 1) * 32;
    const int block_m = blockIdx.x * 128;

    if (tid < 128) s_sm[tid] = 0.f;

    // ---------------- stage 1: conv GEMM (K=128, N=128) ----------------
    float acc[2][8][4];
#pragma unroll
    for (int mf = 0; mf < 2; mf++)
#pragma unroll
        for (int nf = 0; nf < 8; nf++)
#pragma unroll
            for (int qq = 0; qq < 4; qq++) acc[mf][nf][qq] = 0.f;

    copy_tile_A(As[0], A, HH_, block_m, 0, tid, NN_);
    copy_tile_B(Bs[0], W, HH_, 0, tid);
    cp_commit();
    for (int k = 0; k < 4; k++) {
        if (k + 1 < 4) {
            copy_tile_A(As[(k + 1) & 1], A, HH_, block_m, (k + 1) * 32, tid, NN_);
            copy_tile_B(Bs[(k + 1) & 1], W, HH_, (k + 1) * 32, tid);
            cp_commit();
            cp_wait<1>();
        } else {
            cp_wait<0>();
        }
        __syncthreads();
        mma_tile<AK, AK, 8>(As[k & 1], 0, mbase, Bs[k & 1], wn * 64, acc, lane);
        __syncthreads();
    }

    // stage-1 epilogue: hs = acc*din + b; fp16 global write + [row][col] smem
#pragma unroll
    for (int mf = 0; mf < 2; mf++) {
        int rl0 = mbase + mf * 16 + grp;
#pragma unroll
        for (int nf = 0; nf < 8; nf++) {
            int col = wn * 64 + nf * 8 + tig * 2;
            float bc0 = bias[col], bc1 = bias[col + 1];
#pragma unroll
            for (int half = 0; half < 2; half++) {
                int rl = rl0 + half * 8;
                int rg = block_m + rl;
                float rs = (rg < NN_) ? din[rg] : 0.f;
                float v0 = acc[mf][nf][half * 2 + 0] * rs + bc0;
                float v1 = acc[mf][nf][half * 2 + 1] * rs + bc1;
                __half2 hv = __floats2half2_rn(v0, v1);
                *(__half2*)&HSs[rl][col] = hv;
                if (rg < NN_)
                    *(__half2*)(hs_out + (size_t)rg * HH_ + col) = hv;
            }
        }
    }
    __syncthreads();

    // ---------------- stage 2: t = tanh(hs@W1 + b1); s = t.w2 ----------------
    float acc2[2][4][4];
#pragma unroll
    for (int mf = 0; mf < 2; mf++)
#pragma unroll
        for (int nf = 0; nf < 4; nf++)
#pragma unroll
            for (int qq = 0; qq < 4; qq++) acc2[mf][nf][qq] = 0.f;

    for (int k0 = 0; k0 < HH_; k0 += 32) {
        {   // W1 chunk fp16 [n=64][k]: each thread one 16B cp.async
            int n = tid & 63;
            int kb = (tid >> 6) * 8;
            cp16(smem_u32(&Bs[0][n][kb]), W1 + (size_t)n * HH_ + k0 + kb);
            cp_commit();
            cp_wait<0>();
        }
        __syncthreads();
        mma_tile<HSP, AK, 4>(HSs, k0, mbase, Bs[0], wn * 32, acc2, lane);
        __syncthreads();
    }

    float part[2][2] = {{0.f, 0.f}, {0.f, 0.f}};
#pragma unroll
    for (int mf = 0; mf < 2; mf++)
#pragma unroll
        for (int nf = 0; nf < 4; nf++) {
            int col = wn * 32 + nf * 8 + tig * 2;
            float bc0 = b1[col], bc1 = b1[col + 1];
            float w20 = w2[col], w21 = w2[col + 1];
#pragma unroll
            for (int half = 0; half < 2; half++) {
                float v0 = tanhf(acc2[mf][nf][half * 2 + 0] + bc0);
                float v1 = tanhf(acc2[mf][nf][half * 2 + 1] + bc1);
                part[mf][half] += v0 * w20 + v1 * w21;
            }
        }
#pragma unroll
    for (int o = 1; o <= 2; o <<= 1) {
#pragma unroll
        for (int mf = 0; mf < 2; mf++)
#pragma unroll
            for (int half = 0; half < 2; half++)
                part[mf][half] += __shfl_xor_sync(0xffffffffu, part[mf][half], o);
    }
    if (tig == 0) {
#pragma unroll
        for (int mf = 0; mf < 2; mf++)
#pragma unroll
            for (int half = 0; half < 2; half++)
                atomicAdd(&s_sm[mbase + mf * 16 + grp + half * 8], part[mf][half]);
    }
    __syncthreads();
    if (tid < 128) {
        int rg = block_m + tid;
        if (rg < NN_) s_out[rg] = s_sm[tid];
    }
}

// ---------------- batched attention combine (fp16 hs/out) -------------------
template <int PHASE>
__global__ void combine_all_kernel(const __half* __restrict__ hs_all,
                                   const float* __restrict__ s_all,
                                   __half* __restrict__ h1b, __half* __restrict__ hAb,
                                   __half* __restrict__ h2b) {
    const int u = blockIdx.y;
    int q0, c;
    __half* outb;
    if (PHASE == 0) {
        c = u >> 1;
        int li = u & 1;
        q0 = c * 4 + li * 2;
        outb = (li == 0 ? h1b : hAb);
    } else {
        c = u;
        q0 = c * 2;
        outb = h2b;
    }
    const __half* hs0 = hs_all + (size_t)q0 * NH_;
    const __half* hs1 = hs_all + (size_t)(q0 + 1) * NH_;
    const float* s0 = s_all + (size_t)q0 * NN_;
    const float* s1 = s_all + (size_t)(q0 + 1) * NN_;
    __half* out = outb + (size_t)c * NH_;

    int warp = (blockIdx.x * blockDim.x + threadIdx.x) >> 5;
    int lane = threadIdx.x & 31;
    if (warp >= NN_) return;
    float sv0 = s0[warp], sv1 = s1[warp];
    float m = fmaxf(sv0, sv1);
    float e0 = expf(sv0 - m), e1 = expf(sv1 - m);
    float a0 = e0 / (e0 + e1), a1 = 1.f - a0;
    uint2 u0 = ((const uint2*)(hs0 + (size_t)warp * HH_))[lane];
    uint2 u1 = ((const uint2*)(hs1 + (size_t)warp * HH_))[lane];
    float2 f0a = __half22float2(*(__half2*)&u0.x);
    float2 f0b = __half22float2(*(__half2*)&u0.y);
    float2 f1a = __half22float2(*(__half2*)&u1.x);
    float2 f1b = __half22float2(*(__half2*)&u1.y);
    uint2 st;
    *(__half2*)&st.x = __floats2half2_rn(a0 * f0a.x + a1 * f1a.x, a0 * f0a.y + a1 * f1a.y);
    *(__half2*)&st.y = __floats2half2_rn(a0 * f0b.x + a1 * f1b.x, a0 * f0b.y + a1 * f1b.y);
    ((uint2*)(out + (size_t)warp * HH_))[lane] = st;
}

// ---------------- final GEMM: y = [h0|h1|h2](fp16) @ Wc16^T -> fp32 out -----
__global__ __launch_bounds__(256)
void final_gemm_kernel(const __half* __restrict__ h0b, const __half* __restrict__ h1b,
                       const __half* __restrict__ h2b, const __half* __restrict__ wc16,
                       float* __restrict__ Cout) {
    __shared__ __half As[2][128][AK];
    __shared__ __half Bs[2][128][AK];

    const int c = blockIdx.y;
    const int s = c >> 1;
    const __half* B = wc16 + (size_t)s * HH_ * (3 * HH_);
    float* C = Cout + (size_t)c * NH_;

    const int tid  = threadIdx.x;
    const int lane = tid & 31;
    const int warp = tid >> 5;
    const int grp  = lane >> 2;
    const int tig  = lane & 3;
    const int mbase = (warp >> 1) * 32;
    const int nbase = (warp & 1) * 64;
    const int block_m = blockIdx.x * 128;

    const __half* segs[3] = { h0b + (size_t)c * NH_, h1b + (size_t)c * NH_,
                              h2b + (size_t)c * NH_ };

    float acc[2][8][4];
#pragma unroll
    for (int mf = 0; mf < 2; mf++)
#pragma unroll
        for (int nf = 0; nf < 8; nf++)
#pragma unroll
            for (int q = 0; q < 4; q++) acc[mf][nf][q] = 0.f;

    const int NC = 12;
    copy_tile_A(As[0], segs[0], HH_, block_m, 0, tid, NN_);
    copy_tile_B(Bs[0], B, 3 * HH_, 0, tid);
    cp_commit();
    for (int k = 0; k < NC; k++) {
        if (k + 1 < NC) {
            int kn = k + 1;
            copy_tile_A(As[kn & 1], segs[kn >> 2], HH_, block_m, (kn & 3) * 32, tid, NN_);
            copy_tile_B(Bs[kn & 1], B, 3 * HH_, kn * 32, tid);
            cp_commit();
            cp_wait<1>();
        } else {
            cp_wait<0>();
        }
        __syncthreads();
        mma_tile<AK, AK, 8>(As[k & 1], 0, mbase, Bs[k & 1], nbase, acc, lane);
        __syncthreads();
    }
#pragma unroll
    for (int mf = 0; mf < 2; mf++) {
        int r0 = block_m + mbase + mf * 16 + grp;
#pragma unroll
        for (int nf = 0; nf < 8; nf++) {
            int col = nbase + nf * 8 + tig * 2;
#pragma unroll
            for (int half = 0; half < 2; half++) {
                int r = r0 + half * 8;
                if (r >= NN_) continue;
                float2 st;
                st.x = acc[mf][nf][half * 2 + 0];
                st.y = acc[mf][nf][half * 2 + 1];
                *(float2*)(C + (size_t)r * HH_ + col) = st;
            }
        }
    }
}

// ---------------- host orchestration ----------------------------------------
extern "C" void kernel_launch(void* const* d_in, const int* in_sizes, int n_in,
                              void* d_out, int out_size) {
    const float* x_attr  = (const float*)d_in[0];
    const float* x_stru  = (const float*)d_in[1];
    const int*   e_attr  = (const int*)  d_in[2];
    const int*   e_stru  = (const int*)  d_in[3];
    const float* Wf      = (const float*)d_in[4];
    const float* convW   = (const float*)d_in[5];
    const float* convB   = (const float*)d_in[6];
    const float* attnW1  = (const float*)d_in[7];
    const float* attnB1  = (const float*)d_in[8];
    const float* attnW2  = (const float*)d_in[9];
    const float* Wc      = (const float*)d_in[10];
    float* out = (float*)d_out;

    __half *h0, *h1, *hA, *h2, *agg, *hs, *x16, *wf16, *cw16, *w116, *wc16;
    float *sb, *din, *dout;
    int *cnt_in, *cnt_out, *cursor, *off, *csr;
    cudaGetSymbolAddress((void**)&h0,  g_h0);
    cudaGetSymbolAddress((void**)&h1,  g_h1);
    cudaGetSymbolAddress((void**)&hA,  g_hA);
    cudaGetSymbolAddress((void**)&h2,  g_h2);
    cudaGetSymbolAddress((void**)&agg, g_agg);
    cudaGetSymbolAddress((void**)&hs,  g_hs);
    cudaGetSymbolAddress((void**)&sb,  g_s);
    cudaGetSymbolAddress((void**)&x16, g_x16);
    cudaGetSymbolAddress((void**)&wf16, g_wf16);
    cudaGetSymbolAddress((void**)&cw16, g_cw16);
    cudaGetSymbolAddress((void**)&w116, g_w116);
    cudaGetSymbolAddress((void**)&wc16, g_wc16);
    cudaGetSymbolAddress((void**)&din,  g_din);
    cudaGetSymbolAddress((void**)&dout, g_dout);
    cudaGetSymbolAddress((void**)&cnt_in,  g_cnt_in);
    cudaGetSymbolAddress((void**)&cnt_out, g_cnt_out);
    cudaGetSymbolAddress((void**)&cursor,  g_cursor);
    cudaGetSymbolAddress((void**)&off, g_off);
    cudaGetSymbolAddress((void**)&csr, g_csr);

    const int TB = 256;
    const int gridM = (NN_ + 127) / 128;
    const int gridWarp = (NN_ + 7) / 8;
    const int HET_SMEM = 4 * 128 * AK * 2 + 128 * HSP * 2 + 512;   // ~74.5 KB -> 2 blocks/SM
    cudaFuncSetAttribute(het_all_kernel<0>, cudaFuncAttributeMaxDynamicSharedMemorySize, HET_SMEM);
    cudaFuncSetAttribute(het_all_kernel<1>, cudaFuncAttributeMaxDynamicSharedMemorySize, HET_SMEM);

    // 0) prep: weights fp16 [n][k], x fp16
    prep_weights_kernel<<<256, TB>>>(Wf, convW, attnW1, Wc, wf16, cw16, w116, wc16);
    convert_x_kernel<<<512, TB>>>(x_attr, x_stru, x16);

    // 1) zero histogram counters
    zero_int_kernel<<<512, TB>>>(cnt_in, 8 * NN_);
    zero_int_kernel<<<512, TB>>>(cnt_out, 8 * NN_);

    // 2) h0 for all 4 runs (fp16 out)
    h0_gemm_kernel<<<dim3(gridM, 4), TB>>>(x16, wf16, h0);

    // 3) CSR build, all 8 pairs batched
    hist_all_kernel<<<dim3(256, 8), TB>>>(e_attr, e_stru, cnt_out, cnt_in);
    deg_all_kernel<<<(8 * NN_ + 255) / 256, TB>>>(cnt_in, cnt_out, din, dout);
    scan_all_kernel<<<8, 1024>>>(cnt_in, off, cursor);
    scatter_all_kernel<<<dim3(256, 8), TB>>>(e_attr, e_stru, cursor, csr);

    // 4) phase A: gather over h0 (8 pairs), het (16 combos), combine (8)
    gather_all_kernel<<<dim3(gridWarp, 8), TB>>>(h0, off, csr, dout, agg);
    het_all_kernel<0><<<dim3(gridM, 16), TB, HET_SMEM>>>(
        agg, cw16, convB, w116, attnB1, attnW2, din, hs, sb);
    combine_all_kernel<0><<<dim3(gridWarp, 8), TB>>>(hs, sb, h1, hA, h2);

    // 5) phase B: gather over hA (8), het (8), combine (4)
    gather_all_kernel<<<dim3(gridWarp, 8), TB>>>(hA, off, csr, dout, agg);
    het_all_kernel<1><<<dim3(gridM, 8), TB, HET_SMEM>>>(
        agg, cw16, convB, w116, attnB1, attnW2, din, hs, sb);
    combine_all_kernel<1><<<dim3(gridWarp, 4), TB>>>(hs, sb, h1, hA, h2);

    // 6) final: y = [h0|h1|h2] @ Wc^T for all 4 runs (fp32 out)
    final_gemm_kernel<<<dim3(gridM, 4), TB>>>(h0, h1, h2, wc16, out);
}